// round 11
// baseline (speedup 1.0000x reference)
#include <cuda_runtime.h>
#include <cuda_bf16.h>
#include <cstdint>
#include <cstddef>

#define LEN 128
#define HID 64
#define NB 256
#define NN 2048
#define NROWS (NB*NN)          /* 524288 */
#define TILE_M 64
#define NTILES (NROWS/TILE_M)  /* 8192, 32 tiles per batch */
#define NEG_FILL -1.0e9f
#define LN_EPS 1e-3f
#define NTHREADS 256

/* X bf16x2 plane-packed: plane p = q%4 (q = k/2), j = q/4; strides in words */
#define XRST 20                    /* row stride */
#define XPST (TILE_M*XRST + 8)     /* 1288 plane stride */
#define XBUF_WORDS (4*XPST)        /* 5152 per buffer */

/* shared memory (words): consts + 2 X buffers + stats */
#define SM_CG   0
#define SM_CB   128
#define SM_CC   256
#define SM_X0   384
#define SM_X1   (SM_X0 + XBUF_WORDS)
#define SM_ST   (SM_X1 + XBUF_WORDS)
#define SM_WORDS (SM_ST + TILE_M*8)
#define SMEM_BYTES (SM_WORDS*4)    /* 44.8 KB -> 3 CTAs/SM */

/* W fragment-packed in GLOBAL (L1-resident): word index = col*64 + c*16 + tig*4 + w,
   holding bf16x2 of kpair q = 16c + 4w + tig (exact same values R9 read from smem) */
__device__ __align__(16) unsigned g_Wf[128*64];   /* 32 KB */
__device__ float    g_bc[LEN];
__device__ unsigned g_pool[NB*LEN];
__device__ int      g_mask_u8;

__device__ __forceinline__ unsigned f2o(float f){
  unsigned u = __float_as_uint(f);
  return (u & 0x80000000u) ? ~u : (u | 0x80000000u);
}
__device__ __forceinline__ float o2f(unsigned o){
  unsigned u = (o & 0x80000000u) ? (o & 0x7fffffffu) : ~o;
  return __uint_as_float(u);
}
__device__ __forceinline__ unsigned packbf(float lo, float hi){
  unsigned r;
  asm("cvt.rn.bf16x2.f32 %0, %1, %2;" : "=r"(r) : "f"(hi), "f"(lo));
  return r;
}
__device__ __forceinline__ void mma16(float* c, unsigned a0, unsigned a1, unsigned a2,
                                      unsigned a3, unsigned b0, unsigned b1){
  asm volatile(
    "mma.sync.aligned.m16n8k16.row.col.f32.bf16.bf16.f32 "
    "{%0,%1,%2,%3}, {%4,%5,%6,%7}, {%8,%9}, {%0,%1,%2,%3};\n"
    : "+f"(c[0]), "+f"(c[1]), "+f"(c[2]), "+f"(c[3])
    : "r"(a0), "r"(a1), "r"(a2), "r"(a3), "r"(b0), "r"(b1));
}

/* ---- prep: W fragments + bias + pool init + mask probe ---- */
__global__ void prep_kernel(const float* __restrict__ W1, const float* __restrict__ b1,
                            const float* __restrict__ W2, const float* __restrict__ b2,
                            const unsigned* __restrict__ mw){
  if (blockIdx.x == 0){
    __shared__ int flag;
    if (threadIdx.x == 0) flag = 0;
    __syncthreads();
    int loc = 0;
    #pragma unroll
    for (int k = 0; k < 4; k++)
      if (mw[threadIdx.x*4 + k] > 1u) loc = 1;   /* u8-packed bools -> words >1 */
    if (loc) flag = 1;
    __syncthreads();
    if (threadIdx.x == 0) g_mask_u8 = flag;
  }
  int i = blockIdx.x*blockDim.x + threadIdx.x;
  if (i < 128*64){
    int col = i >> 6, c = (i >> 4) & 3, tig = (i >> 2) & 3, w = i & 3;
    int q = 16*c + 4*w + tig;
    int k0 = 2*q, k1 = 2*q + 1;
    float s0 = 0.f, s1 = 0.f;
    #pragma unroll
    for (int h = 0; h < HID; h++){
      s0 += W1[k0*HID + h] * W2[h*LEN + col];
      s1 += W1[k1*HID + h] * W2[h*LEN + col];
    }
    g_Wf[i] = packbf(s0, s1);
  } else if (i < 128*64 + LEN){
    int c = i - 128*64;
    float s = b2[c];
    #pragma unroll
    for (int h = 0; h < HID; h++) s += b1[h] * W2[h*LEN + c];
    g_bc[c] = s;
  } else if (i < 128*64 + LEN + NB*LEN){
    g_pool[i - (128*64 + LEN)] = f2o(NEG_FILL);
  }
}

/* stage one 64x128 fp32 tile -> bf16x2 plane-packed smem (immediate, no held regs) */
__device__ __forceinline__ void stage_tile(unsigned* xb, const float* __restrict__ src,
                                           int row, int seg){
  float4 st[8];
  const float4* gp = (const float4*)(src + row*LEN + seg*32);
  #pragma unroll
  for (int i = 0; i < 8; i++) st[i] = __ldcs(gp + i);
  #pragma unroll
  for (int p = 0; p < 4; p++){
    unsigned w[4];
    #pragma unroll
    for (int jj = 0; jj < 4; jj++){
      int m = p + 4*jj;                 /* kpair q = seg*16 + m */
      float4 v = st[m >> 1];
      float lo = (m & 1) ? v.z : v.x;
      float hi = (m & 1) ? v.w : v.y;
      w[jj] = packbf(lo, hi);
    }
    *(uint4*)(xb + p*XPST + row*XRST + seg*4) = make_uint4(w[0], w[1], w[2], w[3]);
  }
}

/* ---- fused GEMM(bf16) + bias + LN + ReLU + mask + store + pool ---- */
__global__ void __launch_bounds__(NTHREADS,3)
mlp_kernel(const float* __restrict__ X, const void* __restrict__ maskp,
           const float* __restrict__ gamma, const float* __restrict__ beta,
           float* __restrict__ out)
{
  extern __shared__ unsigned smu[];
  float* sGam  = (float*)(smu + SM_CG);
  float* sBet  = (float*)(smu + SM_CB);
  float* sBia  = (float*)(smu + SM_CC);
  float* stats = (float*)(smu + SM_ST);

  const int tid  = threadIdx.x;
  const int lane = tid & 31;
  const int wid  = tid >> 5;
  const int g    = lane >> 2, tig = lane & 3;
  const int wm   = wid >> 2,  wn  = wid & 3;   /* 2 m-warps x 4 n-warps */
  const int cbase = wn*32;
  const int srow = tid >> 2, sseg = tid & 3;

  if (tid < 128){
    sGam[tid] = gamma[tid];
    sBet[tid] = beta[tid];
    sBia[tid] = g_bc[tid];
  }

  const bool mu8 = (g_mask_u8 != 0);
  const unsigned char* m8  = (const unsigned char*)maskp;
  const int*           m32 = (const int*)maskp;

  const int per = (NTILES + gridDim.x - 1) / gridDim.x;
  const int tb  = blockIdx.x * per;
  const int te  = (tb + per < NTILES) ? tb + per : NTILES;
  if (tb >= te) return;

  float pm[8];
  #pragma unroll
  for (int i = 0; i < 8; i++) pm[i] = NEG_FILL;

  /* prologue: stage first tile into buf0 */
  stage_tile(smu + SM_X0, X + (size_t)tb*TILE_M*LEN, srow, sseg);
  __syncthreads();

  for (int t = tb; t < te; t++){
    const int cur = (t - tb) & 1;
    const unsigned* Xs = smu + (cur ? SM_X1 : SM_X0);

    float acc[2][4][4];
    #pragma unroll
    for (int mt = 0; mt < 2; mt++)
      #pragma unroll
      for (int nt = 0; nt < 4; nt++)
        #pragma unroll
        for (int j = 0; j < 4; j++) acc[mt][nt][j] = 0.f;

    #pragma unroll
    for (int c = 0; c < 4; c++){    /* ksteps s = 2c, 2c+1 */
      uint4 a4[4];                  /* rows wm*32 + {g, g+8, 16+g, 24+g} */
      #pragma unroll
      for (int mr = 0; mr < 2; mr++){
        a4[2*mr  ] = *(const uint4*)(Xs + tig*XPST + (wm*32 + mr*16 + g    )*XRST + c*4);
        a4[2*mr+1] = *(const uint4*)(Xs + tig*XPST + (wm*32 + mr*16 + g + 8)*XRST + c*4);
      }
      uint4 w4[4];                  /* W fragments from L1-resident global */
      #pragma unroll
      for (int nt = 0; nt < 4; nt++){
        int col = cbase + nt*8 + g;
        w4[nt] = __ldg((const uint4*)g_Wf + (col*4 + c)*4 + tig);
      }
      #pragma unroll
      for (int nt = 0; nt < 4; nt++){
        mma16(acc[0][nt], a4[0].x, a4[1].x, a4[0].y, a4[1].y, w4[nt].x, w4[nt].y);
        mma16(acc[1][nt], a4[2].x, a4[3].x, a4[2].y, a4[3].y, w4[nt].x, w4[nt].y);
        mma16(acc[0][nt], a4[0].z, a4[1].z, a4[0].w, a4[1].w, w4[nt].z, w4[nt].w);
        mma16(acc[1][nt], a4[2].z, a4[3].z, a4[2].w, a4[3].w, w4[nt].z, w4[nt].w);
      }
    }

    /* bias + LN partial stats */
    #pragma unroll
    for (int mt = 0; mt < 2; mt++){
      float s0=0.f, q0=0.f, s1=0.f, q1=0.f;
      #pragma unroll
      for (int nt = 0; nt < 4; nt++){
        float2 bb = *(const float2*)&sBia[cbase + nt*8 + 2*tig];
        float* a = acc[mt][nt];
        a[0]+=bb.x; a[1]+=bb.y; a[2]+=bb.x; a[3]+=bb.y;
        s0 += a[0]+a[1]; q0 += a[0]*a[0]+a[1]*a[1];
        s1 += a[2]+a[3]; q1 += a[2]*a[2]+a[3]*a[3];
      }
      #pragma unroll
      for (int off = 1; off < 4; off <<= 1){
        s0 += __shfl_xor_sync(0xffffffffu, s0, off);
        q0 += __shfl_xor_sync(0xffffffffu, q0, off);
        s1 += __shfl_xor_sync(0xffffffffu, s1, off);
        q1 += __shfl_xor_sync(0xffffffffu, q1, off);
      }
      if (tig == 0){
        int rb = wm*32 + mt*16;
        stats[(rb+g  )*8 + wn]     = s0;
        stats[(rb+g  )*8 + 4 + wn] = q0;
        stats[(rb+g+8)*8 + wn]     = s1;
        stats[(rb+g+8)*8 + 4 + wn] = q1;
      }
    }
    __syncthreads();                                  /* (B) stats ready; Xs reads done */

    const size_t growbase = (size_t)t * TILE_M;
    #pragma unroll
    for (int mt = 0; mt < 2; mt++){
      const int rb = wm*32 + mt*16;
      const int rg = rb + g, rg8 = rb + g + 8;
      float4 su4a = *(const float4*)&stats[rg *8];
      float4 sq4a = *(const float4*)&stats[rg *8 + 4];
      float4 su4b = *(const float4*)&stats[rg8*8];
      float4 sq4b = *(const float4*)&stats[rg8*8 + 4];
      float sua = su4a.x+su4a.y+su4a.z+su4a.w, sqa = sq4a.x+sq4a.y+sq4a.z+sq4a.w;
      float sub = su4b.x+su4b.y+su4b.z+su4b.w, sqb = sq4b.x+sq4b.y+sq4b.z+sq4b.w;
      float mua = sua * (1.0f/LEN), mub = sub * (1.0f/LEN);
      float rsa = rsqrtf(fmaxf(sqa*(1.0f/LEN) - mua*mua, 0.f) + LN_EPS);
      float rsb = rsqrtf(fmaxf(sqb*(1.0f/LEN) - mub*mub, 0.f) + LN_EPS);
      bool mka = mu8 ? (m8[growbase+rg ] != 0) : (m32[growbase+rg ] != 0);
      bool mkb = mu8 ? (m8[growbase+rg8] != 0) : (m32[growbase+rg8] != 0);
      float* orowa = out + (growbase + rg ) * (2*LEN);
      float* orowb = out + (growbase + rg8) * (2*LEN);
      #pragma unroll
      for (int nt = 0; nt < 4; nt++){
        const int c0 = cbase + nt*8 + 2*tig;
        float2 gg = *(const float2*)&sGam[c0];
        float2 be = *(const float2*)&sBet[c0];
        float* a = acc[mt][nt];
        float v0 = (a[0]-mua)*rsa*gg.x + be.x;
        float v1 = (a[1]-mua)*rsa*gg.y + be.y;
        float v2 = (a[2]-mub)*rsb*gg.x + be.x;
        float v3 = (a[3]-mub)*rsb*gg.y + be.y;
        v0 = mka ? fmaxf(v0, 0.f) : NEG_FILL;
        v1 = mka ? fmaxf(v1, 0.f) : NEG_FILL;
        v2 = mkb ? fmaxf(v2, 0.f) : NEG_FILL;
        v3 = mkb ? fmaxf(v3, 0.f) : NEG_FILL;
        __stcs((float2*)(orowa + c0), make_float2(v0, v1));
        __stcs((float2*)(orowb + c0), make_float2(v2, v3));
        pm[2*nt]   = fmaxf(pm[2*nt],   fmaxf(v0, v2));
        pm[2*nt+1] = fmaxf(pm[2*nt+1], fmaxf(v1, v3));
      }
    }

    /* stage next tile into the other buffer (transient regs) */
    if (t + 1 < te)
      stage_tile((unsigned*)(smu + (cur ? SM_X0 : SM_X1)),
                 X + (size_t)(t+1)*TILE_M*LEN, srow, sseg);

    /* batch boundary (32 tiles/batch): flush pool */
    if (t == te-1 || ((t+1) >> 5) != (t >> 5)){
      const int b = t >> 5;
      #pragma unroll
      for (int i = 0; i < 8; i++){
        pm[i] = fmaxf(pm[i], __shfl_xor_sync(0xffffffffu, pm[i], 4));
        pm[i] = fmaxf(pm[i], __shfl_xor_sync(0xffffffffu, pm[i], 8));
        pm[i] = fmaxf(pm[i], __shfl_xor_sync(0xffffffffu, pm[i], 16));
      }
      if (lane < 4){   /* g==0 lanes: tig = lane */
        unsigned* pp = g_pool + b*LEN;
        #pragma unroll
        for (int nt = 0; nt < 4; nt++){
          int c0 = cbase + nt*8 + 2*lane;
          atomicMax(pp + c0,     f2o(pm[2*nt]));
          atomicMax(pp + c0 + 1, f2o(pm[2*nt+1]));
        }
      }
      #pragma unroll
      for (int i = 0; i < 8; i++) pm[i] = NEG_FILL;
    }
    __syncthreads();   /* staged buffer complete before next iter reads it */
  }
}

/* ---- broadcast pooled max into second half of output ---- */
__global__ void __launch_bounds__(256,8)
broadcast_kernel(float* __restrict__ out){
  const int b   = blockIdx.x >> 3;          /* batch */
  const int rch = (blockIdx.x & 7) * 256;   /* row chunk within batch */
  const int c4  = threadIdx.x & 31;
  const int w   = threadIdx.x >> 5;
  uint4 p = *(const uint4*)(g_pool + b*LEN + c4*4);
  float4 v = make_float4(o2f(p.x), o2f(p.y), o2f(p.z), o2f(p.w));
  float* base = out + ((size_t)b*NN + rch) * (2*LEN) + LEN + c4*4;
  #pragma unroll
  for (int it = 0; it < 32; it++)
    __stcs((float4*)(base + (size_t)(w + it*8) * (2*LEN)), v);
}

extern "C" void kernel_launch(void* const* d_in, const int* in_sizes, int n_in,
                              void* d_out, int out_size){
  (void)in_sizes; (void)n_in; (void)out_size;
  const float* X    = (const float*)d_in[0];
  const void*  mask = d_in[1];
  const float* W1   = (const float*)d_in[2];
  const float* b1   = (const float*)d_in[3];
  const float* W2   = (const float*)d_in[4];
  const float* b2   = (const float*)d_in[5];
  const float* gm   = (const float*)d_in[6];
  const float* bt   = (const float*)d_in[7];
  float* out = (float*)d_out;

  cudaFuncSetAttribute(mlp_kernel, cudaFuncAttributeMaxDynamicSharedMemorySize, SMEM_BYTES);

  int dev = 0; cudaGetDevice(&dev);
  int sms = 148;
  cudaDeviceGetAttribute(&sms, cudaDevAttrMultiProcessorCount, dev);
  if (sms <= 0) sms = 148;

  prep_kernel<<<(128*64 + LEN + NB*LEN + 255)/256, 256>>>(W1, b1, W2, b2,
                                                          (const unsigned*)mask);
  mlp_kernel<<<sms*3, NTHREADS, SMEM_BYTES>>>(X, mask, gm, bt, out);
  broadcast_kernel<<<NB*8, 256>>>(out);
}

// round 12
// speedup vs baseline: 1.1342x; 1.1342x over previous
#include <cuda_runtime.h>
#include <cuda_bf16.h>
#include <cstdint>
#include <cstddef>

#define LEN 128
#define HID 64
#define NB 256
#define NN 2048
#define NROWS (NB*NN)          /* 524288 */
#define TILE_M 128
#define NTILES (NROWS/TILE_M)  /* 4096, 16 tiles per batch */
#define NEG_FILL -1.0e9f
#define LN_EPS 1e-3f
#define NTHREADS 512

/* bf16x2 plane-packed layouts over kpair q (=k/2, 0..63): plane p=q%4, j=q/4.
   Strides in 32-bit words. */
#define WCST 20                    /* W col stride */
#define WPST (128*WCST + 8)        /* 2568 W plane stride */
#define WP_WORDS (4*WPST)          /* 10272 */
#define XRST 20                    /* X row stride */
#define XPST (TILE_M*XRST + 8)     /* 2568 X plane stride */
#define XBUF_WORDS (4*XPST)        /* 10272 per buffer */

/* shared memory layout (words) */
#define SM_W    0
#define SM_CG   WP_WORDS
#define SM_CB   (SM_CG + 128)
#define SM_CC   (SM_CB + 128)
#define SM_X0   (SM_CC + 128)
#define SM_X1   (SM_X0 + XBUF_WORDS)
#define SM_ST   (SM_X1 + XBUF_WORDS)
#define SM_WORDS (SM_ST + TILE_M*8)
#define SMEM_BYTES (SM_WORDS*4)    /* ~127.7 KB */

__device__ __align__(16) unsigned g_Wpu[WP_WORDS]; /* combined W1@W2 bf16x2, plane-packed */
__device__ float    g_bc[LEN];
__device__ unsigned g_pool[NB*LEN];
__device__ int      g_mask_u8;

__device__ __forceinline__ unsigned f2o(float f){
  unsigned u = __float_as_uint(f);
  return (u & 0x80000000u) ? ~u : (u | 0x80000000u);
}
__device__ __forceinline__ float o2f(unsigned o){
  unsigned u = (o & 0x80000000u) ? (o & 0x7fffffffu) : ~o;
  return __uint_as_float(u);
}
__device__ __forceinline__ unsigned packbf(float lo, float hi){
  unsigned r;
  asm("cvt.rn.bf16x2.f32 %0, %1, %2;" : "=r"(r) : "f"(hi), "f"(lo));
  return r;
}
__device__ __forceinline__ void mma16(float* c, unsigned a0, unsigned a1, unsigned a2,
                                      unsigned a3, unsigned b0, unsigned b1){
  asm volatile(
    "mma.sync.aligned.m16n8k16.row.col.f32.bf16.bf16.f32 "
    "{%0,%1,%2,%3}, {%4,%5,%6,%7}, {%8,%9}, {%0,%1,%2,%3};\n"
    : "+f"(c[0]), "+f"(c[1]), "+f"(c[2]), "+f"(c[3])
    : "r"(a0), "r"(a1), "r"(a2), "r"(a3), "r"(b0), "r"(b1));
}

/* ---- prep: combined weight (bf16x2 plane layout) + bias + pool init + mask probe ---- */
__global__ void prep_kernel(const float* __restrict__ W1, const float* __restrict__ b1,
                            const float* __restrict__ W2, const float* __restrict__ b2,
                            const unsigned* __restrict__ mw){
  if (blockIdx.x == 0){
    __shared__ int flag;
    if (threadIdx.x == 0) flag = 0;
    __syncthreads();
    int loc = 0;
    #pragma unroll
    for (int k = 0; k < 4; k++)
      if (mw[threadIdx.x*4 + k] > 1u) loc = 1;   /* u8-packed bools -> words >1 */
    if (loc) flag = 1;
    __syncthreads();
    if (threadIdx.x == 0) g_mask_u8 = flag;
  }
  int i = blockIdx.x*blockDim.x + threadIdx.x;
  if (i < 128*64){                      /* col x kpair */
    int col = i >> 6, q = i & 63;
    int k0 = 2*q, k1 = 2*q + 1;
    float s0 = 0.f, s1 = 0.f;
    #pragma unroll
    for (int h = 0; h < HID; h++){
      s0 += W1[k0*HID + h] * W2[h*LEN + col];
      s1 += W1[k1*HID + h] * W2[h*LEN + col];
    }
    g_Wpu[(q&3)*WPST + col*WCST + (q>>2)] = packbf(s0, s1);
  } else if (i < 128*64 + LEN){
    int c = i - 128*64;
    float s = b2[c];
    #pragma unroll
    for (int h = 0; h < HID; h++) s += b1[h] * W2[h*LEN + c];
    g_bc[c] = s;
  } else if (i < 128*64 + LEN + NB*LEN){
    g_pool[i - (128*64 + LEN)] = f2o(NEG_FILL);
  }
}

/* stage one 128x128 fp32 tile -> bf16x2 plane-packed smem (transient registers) */
__device__ __forceinline__ void stage_tile(unsigned* xb, const float* __restrict__ src,
                                           int row, int seg){
  float4 st[8];
  const float4* gp = (const float4*)(src + row*LEN + seg*32);
  #pragma unroll
  for (int i = 0; i < 8; i++) st[i] = __ldcs(gp + i);   /* 8 pipelined LDG.128 */
  #pragma unroll
  for (int p = 0; p < 4; p++){
    unsigned w[4];
    #pragma unroll
    for (int jj = 0; jj < 4; jj++){
      int m = p + 4*jj;                 /* kpair q = seg*16 + m */
      float4 v = st[m >> 1];
      float lo = (m & 1) ? v.z : v.x;
      float hi = (m & 1) ? v.w : v.y;
      w[jj] = packbf(lo, hi);
    }
    *(uint4*)(xb + p*XPST + row*XRST + seg*4) = make_uint4(w[0], w[1], w[2], w[3]);
  }
}

/* ---- fused GEMM(bf16) + bias + LN + ReLU + mask + direct store + pooled max ---- */
__global__ void __launch_bounds__(NTHREADS,1)
mlp_kernel(const float* __restrict__ X, const void* __restrict__ maskp,
           const float* __restrict__ gamma, const float* __restrict__ beta,
           float* __restrict__ out)
{
  extern __shared__ unsigned smu[];
  unsigned* Wp   = smu + SM_W;
  float* sGam    = (float*)(smu + SM_CG);
  float* sBet    = (float*)(smu + SM_CB);
  float* sBia    = (float*)(smu + SM_CC);
  float* stats   = (float*)(smu + SM_ST);

  const int tid  = threadIdx.x;
  const int lane = tid & 31;
  const int wid  = tid >> 5;
  const int g    = lane >> 2, tig = lane & 3;
  const int wm   = wid >> 2,  wn  = wid & 3;   /* 4 m-warps x 4 n-warps */
  const int cbase = wn*32;
  const int srow = tid >> 2, sseg = tid & 3;   /* staging coords: 128 rows x 4 segs */

  #pragma unroll
  for (int i = tid; i < WP_WORDS/4; i += NTHREADS)
    ((uint4*)Wp)[i] = ((const uint4*)g_Wpu)[i];
  if (tid < 128){
    sGam[tid] = gamma[tid];
    sBet[tid] = beta[tid];
    sBia[tid] = g_bc[tid];
  }

  const bool mu8 = (g_mask_u8 != 0);
  const unsigned char* m8  = (const unsigned char*)maskp;
  const int*           m32 = (const int*)maskp;

  const int per = (NTILES + gridDim.x - 1) / gridDim.x;
  const int tb  = blockIdx.x * per;
  const int te  = (tb + per < NTILES) ? tb + per : NTILES;
  if (tb >= te) return;

  float pm[8];
  #pragma unroll
  for (int i = 0; i < 8; i++) pm[i] = NEG_FILL;

  /* prologue: stage first tile into buf0 */
  stage_tile(smu + SM_X0, X + (size_t)tb*TILE_M*LEN, srow, sseg);
  __syncthreads();

  for (int t = tb; t < te; t++){
    const int cur = (t - tb) & 1;
    const unsigned* Xs = smu + (cur ? SM_X1 : SM_X0);

    float acc[2][4][4];
    #pragma unroll
    for (int mt = 0; mt < 2; mt++)
      #pragma unroll
      for (int nt = 0; nt < 4; nt++)
        #pragma unroll
        for (int j = 0; j < 4; j++) acc[mt][nt][j] = 0.f;

    #pragma unroll
    for (int c = 0; c < 4; c++){    /* ksteps s = 2c, 2c+1 */
      uint4 a4[4];                  /* rows wm*32 + {g, g+8, 16+g, 24+g} */
      #pragma unroll
      for (int mr = 0; mr < 2; mr++){
        a4[2*mr  ] = *(const uint4*)(Xs + tig*XPST + (wm*32 + mr*16 + g    )*XRST + c*4);
        a4[2*mr+1] = *(const uint4*)(Xs + tig*XPST + (wm*32 + mr*16 + g + 8)*XRST + c*4);
      }
      uint4 w4[4];
      #pragma unroll
      for (int nt = 0; nt < 4; nt++)
        w4[nt] = *(const uint4*)(Wp + tig*WPST + (cbase + nt*8 + g)*WCST + c*4);
      #pragma unroll
      for (int nt = 0; nt < 4; nt++){
        mma16(acc[0][nt], a4[0].x, a4[1].x, a4[0].y, a4[1].y, w4[nt].x, w4[nt].y);
        mma16(acc[1][nt], a4[2].x, a4[3].x, a4[2].y, a4[3].y, w4[nt].x, w4[nt].y);
        mma16(acc[0][nt], a4[0].z, a4[1].z, a4[0].w, a4[1].w, w4[nt].z, w4[nt].w);
        mma16(acc[1][nt], a4[2].z, a4[3].z, a4[2].w, a4[3].w, w4[nt].z, w4[nt].w);
      }
    }

    /* bias + LN partial stats */
    #pragma unroll
    for (int mt = 0; mt < 2; mt++){
      float s0=0.f, q0=0.f, s1=0.f, q1=0.f;
      #pragma unroll
      for (int nt = 0; nt < 4; nt++){
        float2 bb = *(const float2*)&sBia[cbase + nt*8 + 2*tig];
        float* a = acc[mt][nt];
        a[0]+=bb.x; a[1]+=bb.y; a[2]+=bb.x; a[3]+=bb.y;
        s0 += a[0]+a[1]; q0 += a[0]*a[0]+a[1]*a[1];
        s1 += a[2]+a[3]; q1 += a[2]*a[2]+a[3]*a[3];
      }
      #pragma unroll
      for (int off = 1; off < 4; off <<= 1){
        s0 += __shfl_xor_sync(0xffffffffu, s0, off);
        q0 += __shfl_xor_sync(0xffffffffu, q0, off);
        s1 += __shfl_xor_sync(0xffffffffu, s1, off);
        q1 += __shfl_xor_sync(0xffffffffu, q1, off);
      }
      if (tig == 0){
        int rb = wm*32 + mt*16;
        stats[(rb+g  )*8 + wn]     = s0;
        stats[(rb+g  )*8 + 4 + wn] = q0;
        stats[(rb+g+8)*8 + wn]     = s1;
        stats[(rb+g+8)*8 + 4 + wn] = q1;
      }
    }
    __syncthreads();                                  /* (B) stats ready; Xs reads done */

    const size_t growbase = (size_t)t * TILE_M;
    #pragma unroll
    for (int mt = 0; mt < 2; mt++){
      const int rb = wm*32 + mt*16;
      const int rg = rb + g, rg8 = rb + g + 8;
      float4 su4a = *(const float4*)&stats[rg *8];
      float4 sq4a = *(const float4*)&stats[rg *8 + 4];
      float4 su4b = *(const float4*)&stats[rg8*8];
      float4 sq4b = *(const float4*)&stats[rg8*8 + 4];
      float sua = su4a.x+su4a.y+su4a.z+su4a.w, sqa = sq4a.x+sq4a.y+sq4a.z+sq4a.w;
      float sub = su4b.x+su4b.y+su4b.z+su4b.w, sqb = sq4b.x+sq4b.y+sq4b.z+sq4b.w;
      float mua = sua * (1.0f/LEN), mub = sub * (1.0f/LEN);
      float rsa = rsqrtf(fmaxf(sqa*(1.0f/LEN) - mua*mua, 0.f) + LN_EPS);
      float rsb = rsqrtf(fmaxf(sqb*(1.0f/LEN) - mub*mub, 0.f) + LN_EPS);
      bool mka = mu8 ? (m8[growbase+rg ] != 0) : (m32[growbase+rg ] != 0);
      bool mkb = mu8 ? (m8[growbase+rg8] != 0) : (m32[growbase+rg8] != 0);
      float* orowa = out + (growbase + rg ) * (2*LEN);
      float* orowb = out + (growbase + rg8) * (2*LEN);
      #pragma unroll
      for (int nt = 0; nt < 4; nt++){
        const int c0 = cbase + nt*8 + 2*tig;
        float2 gg = *(const float2*)&sGam[c0];
        float2 be = *(const float2*)&sBet[c0];
        float* a = acc[mt][nt];
        float v0 = (a[0]-mua)*rsa*gg.x + be.x;
        float v1 = (a[1]-mua)*rsa*gg.y + be.y;
        float v2 = (a[2]-mub)*rsb*gg.x + be.x;
        float v3 = (a[3]-mub)*rsb*gg.y + be.y;
        v0 = mka ? fmaxf(v0, 0.f) : NEG_FILL;
        v1 = mka ? fmaxf(v1, 0.f) : NEG_FILL;
        v2 = mkb ? fmaxf(v2, 0.f) : NEG_FILL;
        v3 = mkb ? fmaxf(v3, 0.f) : NEG_FILL;
        __stcs((float2*)(orowa + c0), make_float2(v0, v1));
        __stcs((float2*)(orowb + c0), make_float2(v2, v3));
        pm[2*nt]   = fmaxf(pm[2*nt],   fmaxf(v0, v2));
        pm[2*nt+1] = fmaxf(pm[2*nt+1], fmaxf(v1, v3));
      }
    }

    /* stage next tile into the other buffer (transient regs, loads pipeline) */
    if (t + 1 < te)
      stage_tile((unsigned*)(smu + (cur ? SM_X0 : SM_X1)),
                 X + (size_t)(t+1)*TILE_M*LEN, srow, sseg);

    /* batch boundary (16 tiles/batch): flush pool */
    if (t == te-1 || ((t+1) >> 4) != (t >> 4)){
      #pragma unroll
      for (int i = 0; i < 8; i++){
        pm[i] = fmaxf(pm[i], __shfl_xor_sync(0xffffffffu, pm[i], 4));
        pm[i] = fmaxf(pm[i], __shfl_xor_sync(0xffffffffu, pm[i], 8));
        pm[i] = fmaxf(pm[i], __shfl_xor_sync(0xffffffffu, pm[i], 16));
      }
      if (lane < 4){   /* g==0 lanes: tig = lane */
        unsigned* pp = g_pool + (t >> 4)*LEN;
        #pragma unroll
        for (int nt = 0; nt < 4; nt++){
          int c0 = cbase + nt*8 + 2*lane;
          atomicMax(pp + c0,     f2o(pm[2*nt]));
          atomicMax(pp + c0 + 1, f2o(pm[2*nt+1]));
        }
      }
      #pragma unroll
      for (int i = 0; i < 8; i++) pm[i] = NEG_FILL;
    }
    __syncthreads();   /* staged buffer complete before next iter reads it */
  }
}

/* ---- broadcast pooled max into second half of output ---- */
__global__ void __launch_bounds__(256,8)
broadcast_kernel(float* __restrict__ out){
  const int b   = blockIdx.x >> 3;          /* batch */
  const int rch = (blockIdx.x & 7) * 256;   /* row chunk within batch */
  const int c4  = threadIdx.x & 31;
  const int w   = threadIdx.x >> 5;
  uint4 p = *(const uint4*)(g_pool + b*LEN + c4*4);
  float4 v = make_float4(o2f(p.x), o2f(p.y), o2f(p.z), o2f(p.w));
  float* base = out + ((size_t)b*NN + rch) * (2*LEN) + LEN + c4*4;
  #pragma unroll
  for (int it = 0; it < 32; it++)
    __stcs((float4*)(base + (size_t)(w + it*8) * (2*LEN)), v);
}

extern "C" void kernel_launch(void* const* d_in, const int* in_sizes, int n_in,
                              void* d_out, int out_size){
  (void)in_sizes; (void)n_in; (void)out_size;
  const float* X    = (const float*)d_in[0];
  const void*  mask = d_in[1];
  const float* W1   = (const float*)d_in[2];
  const float* b1   = (const float*)d_in[3];
  const float* W2   = (const float*)d_in[4];
  const float* b2   = (const float*)d_in[5];
  const float* gm   = (const float*)d_in[6];
  const float* bt   = (const float*)d_in[7];
  float* out = (float*)d_out;

  cudaFuncSetAttribute(mlp_kernel, cudaFuncAttributeMaxDynamicSharedMemorySize, SMEM_BYTES);

  int dev = 0; cudaGetDevice(&dev);
  int sms = 148;
  cudaDeviceGetAttribute(&sms, cudaDevAttrMultiProcessorCount, dev);
  if (sms <= 0) sms = 148;

  prep_kernel<<<(128*64 + LEN + NB*LEN + 255)/256, 256>>>(W1, b1, W2, b2,
                                                          (const unsigned*)mask);
  mlp_kernel<<<sms, NTHREADS, SMEM_BYTES>>>(X, mask, gm, bt, out);
  broadcast_kernel<<<NB*8, 256>>>(out);
}

// round 13
// speedup vs baseline: 1.4174x; 1.2497x over previous
#include <cuda_runtime.h>
#include <cuda_bf16.h>
#include <cstdint>
#include <cstddef>

#define LEN 128
#define HID 64
#define NB 256
#define NN 2048
#define NROWS (NB*NN)          /* 524288 */
#define TILE_M 64
#define NTILES (NROWS/TILE_M)  /* 8192, 32 tiles per batch */
#define NEG_FILL -1.0e9f
#define LN_EPS 1e-3f
#define NTHREADS 512

/* bf16x2 plane-packed layouts over kpair q (=k/2, 0..63): plane p=q%4, j=q/4.
   Strides in 32-bit words. */
#define WCST 20                    /* W col stride */
#define WPST (128*WCST + 8)        /* 2568 W plane stride */
#define WP_WORDS (4*WPST)          /* 10272 */
#define XRST 20                    /* X row stride */
#define XPST (TILE_M*XRST + 8)     /* 1288 X plane stride */
#define XBUF_WORDS (4*XPST)        /* 5152 per buffer */

/* shared memory layout (words) */
#define SM_W    0
#define SM_CG   WP_WORDS
#define SM_CB   (SM_CG + 128)
#define SM_CC   (SM_CB + 128)
#define SM_X0   (SM_CC + 128)
#define SM_X1   (SM_X0 + XBUF_WORDS)
#define SM_ST   (SM_X1 + XBUF_WORDS)
#define SM_WORDS (SM_ST + TILE_M*8)
#define SMEM_BYTES (SM_WORDS*4)    /* ~86 KB -> 2 CTAs/SM */

__device__ __align__(16) unsigned g_Wpu[WP_WORDS]; /* combined W1@W2 bf16x2, plane-packed */
__device__ float    g_bc[LEN];
__device__ unsigned g_pool[NB*LEN];
__device__ int      g_mask_u8;

__device__ __forceinline__ unsigned f2o(float f){
  unsigned u = __float_as_uint(f);
  return (u & 0x80000000u) ? ~u : (u | 0x80000000u);
}
__device__ __forceinline__ float o2f(unsigned o){
  unsigned u = (o & 0x80000000u) ? (o & 0x7fffffffu) : ~o;
  return __uint_as_float(u);
}
__device__ __forceinline__ unsigned packbf(float lo, float hi){
  unsigned r;
  asm("cvt.rn.bf16x2.f32 %0, %1, %2;" : "=r"(r) : "f"(hi), "f"(lo));
  return r;
}
__device__ __forceinline__ void mma16(float* c, unsigned a0, unsigned a1, unsigned a2,
                                      unsigned a3, unsigned b0, unsigned b1){
  asm volatile(
    "mma.sync.aligned.m16n8k16.row.col.f32.bf16.bf16.f32 "
    "{%0,%1,%2,%3}, {%4,%5,%6,%7}, {%8,%9}, {%0,%1,%2,%3};\n"
    : "+f"(c[0]), "+f"(c[1]), "+f"(c[2]), "+f"(c[3])
    : "r"(a0), "r"(a1), "r"(a2), "r"(a3), "r"(b0), "r"(b1));
}

/* ---- prep: combined weight (bf16x2 plane layout) + bias + pool init + mask probe ---- */
__global__ void prep_kernel(const float* __restrict__ W1, const float* __restrict__ b1,
                            const float* __restrict__ W2, const float* __restrict__ b2,
                            const unsigned* __restrict__ mw){
  if (blockIdx.x == 0){
    __shared__ int flag;
    if (threadIdx.x == 0) flag = 0;
    __syncthreads();
    int loc = 0;
    #pragma unroll
    for (int k = 0; k < 4; k++)
      if (mw[threadIdx.x*4 + k] > 1u) loc = 1;   /* u8-packed bools -> words >1 */
    if (loc) flag = 1;
    __syncthreads();
    if (threadIdx.x == 0) g_mask_u8 = flag;
  }
  int i = blockIdx.x*blockDim.x + threadIdx.x;
  if (i < 128*64){                      /* col x kpair */
    int col = i >> 6, q = i & 63;
    int k0 = 2*q, k1 = 2*q + 1;
    float s0 = 0.f, s1 = 0.f;
    #pragma unroll
    for (int h = 0; h < HID; h++){
      s0 += W1[k0*HID + h] * W2[h*LEN + col];
      s1 += W1[k1*HID + h] * W2[h*LEN + col];
    }
    g_Wpu[(q&3)*WPST + col*WCST + (q>>2)] = packbf(s0, s1);
  } else if (i < 128*64 + LEN){
    int c = i - 128*64;
    float s = b2[c];
    #pragma unroll
    for (int h = 0; h < HID; h++) s += b1[h] * W2[h*LEN + c];
    g_bc[c] = s;
  } else if (i < 128*64 + LEN + NB*LEN){
    g_pool[i - (128*64 + LEN)] = f2o(NEG_FILL);
  }
}

/* STS one held tile (4 float4/thread) -> bf16x2 plane-packed buffer */
__device__ __forceinline__ void sts_held(unsigned* xb, const float4* st, int row, int cb){
  #pragma unroll
  for (int i = 0; i < 4; i++){
    int c = cb + 8*i;                /* chunk: floats 4c..4c+3, kpairs 2c, 2c+1 */
    float4 v = st[i];
    int q0 = 2*c, q1 = 2*c + 1;
    xb[(q0&3)*XPST + row*XRST + (q0>>2)] = packbf(v.x, v.y);
    xb[(q1&3)*XPST + row*XRST + (q1>>2)] = packbf(v.z, v.w);
  }
}
__device__ __forceinline__ void ldg_tile(float4* st, const float* __restrict__ src,
                                         int row, int cb){
  #pragma unroll
  for (int i = 0; i < 4; i++)
    st[i] = __ldcs((const float4*)(src + row*LEN + (cb + 8*i)*4));
}

/* ---- fused GEMM(bf16) + bias + LN + ReLU + mask + direct store + pooled max ---- */
__global__ void __launch_bounds__(NTHREADS,2)
mlp_kernel(const float* __restrict__ X, const void* __restrict__ maskp,
           const float* __restrict__ gamma, const float* __restrict__ beta,
           float* __restrict__ out)
{
  extern __shared__ unsigned smu[];
  unsigned* Wp   = smu + SM_W;
  float* sGam    = (float*)(smu + SM_CG);
  float* sBet    = (float*)(smu + SM_CB);
  float* sBia    = (float*)(smu + SM_CC);
  float* stats   = (float*)(smu + SM_ST);

  const int tid  = threadIdx.x;
  const int lane = tid & 31;
  const int wid  = tid >> 5;
  const int g    = lane >> 2, tig = lane & 3;
  const int wm   = wid >> 2,  wn  = wid & 3;   /* 4 m-warps x 4 n-warps; 16 rows/m-warp */
  const int cbase = wn*32;
  const int rb   = wm*16;
  const int srow = tid >> 3, scb = tid & 7;    /* staging: 64 rows x 8 base-chunks */

  #pragma unroll
  for (int i = tid; i < WP_WORDS/4; i += NTHREADS)
    ((uint4*)Wp)[i] = ((const uint4*)g_Wpu)[i];
  if (tid < 128){
    sGam[tid] = gamma[tid];
    sBet[tid] = beta[tid];
    sBia[tid] = g_bc[tid];
  }

  const bool mu8 = (g_mask_u8 != 0);
  const unsigned char* m8  = (const unsigned char*)maskp;
  const int*           m32 = (const int*)maskp;

  const int per = (NTILES + gridDim.x - 1) / gridDim.x;
  const int tb  = blockIdx.x * per;
  const int te  = (tb + per < NTILES) ? tb + per : NTILES;
  if (tb >= te) return;

  float pm[8];
  #pragma unroll
  for (int i = 0; i < 8; i++) pm[i] = NEG_FILL;

  float4 st[4];
  /* prologue: stage tile tb into buf0 (transient), then issue LDG for tb+1 */
  ldg_tile(st, X + (size_t)tb*TILE_M*LEN, srow, scb);
  sts_held(smu + SM_X0, st, srow, scb);
  if (tb + 1 < te) ldg_tile(st, X + (size_t)(tb+1)*TILE_M*LEN, srow, scb);
  __syncthreads();

  for (int t = tb; t < te; t++){
    const int cur = (t - tb) & 1;
    const unsigned* Xs = smu + (cur ? SM_X1 : SM_X0);

    float acc[4][4];
    #pragma unroll
    for (int nt = 0; nt < 4; nt++)
      #pragma unroll
      for (int j = 0; j < 4; j++) acc[nt][j] = 0.f;

    #pragma unroll
    for (int c = 0; c < 4; c++){    /* ksteps s = 2c, 2c+1 */
      uint4 a0 = *(const uint4*)(Xs + tig*XPST + (rb + g    )*XRST + c*4);
      uint4 a1 = *(const uint4*)(Xs + tig*XPST + (rb + g + 8)*XRST + c*4);
      uint4 w4[4];
      #pragma unroll
      for (int nt = 0; nt < 4; nt++)
        w4[nt] = *(const uint4*)(Wp + tig*WPST + (cbase + nt*8 + g)*WCST + c*4);
      #pragma unroll
      for (int nt = 0; nt < 4; nt++){
        mma16(acc[nt], a0.x, a1.x, a0.y, a1.y, w4[nt].x, w4[nt].y);
        mma16(acc[nt], a0.z, a1.z, a0.w, a1.w, w4[nt].z, w4[nt].w);
      }
    }

    /* bias + LN partial stats */
    {
      float s0=0.f, q0=0.f, s1=0.f, q1=0.f;
      #pragma unroll
      for (int nt = 0; nt < 4; nt++){
        float2 bb = *(const float2*)&sBia[cbase + nt*8 + 2*tig];
        float* a = acc[nt];
        a[0]+=bb.x; a[1]+=bb.y; a[2]+=bb.x; a[3]+=bb.y;
        s0 += a[0]+a[1]; q0 += a[0]*a[0]+a[1]*a[1];
        s1 += a[2]+a[3]; q1 += a[2]*a[2]+a[3]*a[3];
      }
      #pragma unroll
      for (int off = 1; off < 4; off <<= 1){
        s0 += __shfl_xor_sync(0xffffffffu, s0, off);
        q0 += __shfl_xor_sync(0xffffffffu, q0, off);
        s1 += __shfl_xor_sync(0xffffffffu, s1, off);
        q1 += __shfl_xor_sync(0xffffffffu, q1, off);
      }
      if (tig == 0){
        stats[(rb+g  )*8 + wn]     = s0;
        stats[(rb+g  )*8 + 4 + wn] = q0;
        stats[(rb+g+8)*8 + wn]     = s1;
        stats[(rb+g+8)*8 + 4 + wn] = q1;
      }
    }
    __syncthreads();                                  /* (B) stats ready; Xs reads done */

    const size_t growbase = (size_t)t * TILE_M;
    {
      const int rg = rb + g, rg8 = rb + g + 8;
      float4 su4a = *(const float4*)&stats[rg *8];
      float4 sq4a = *(const float4*)&stats[rg *8 + 4];
      float4 su4b = *(const float4*)&stats[rg8*8];
      float4 sq4b = *(const float4*)&stats[rg8*8 + 4];
      float sua = su4a.x+su4a.y+su4a.z+su4a.w, sqa = sq4a.x+sq4a.y+sq4a.z+sq4a.w;
      float sub = su4b.x+su4b.y+su4b.z+su4b.w, sqb = sq4b.x+sq4b.y+sq4b.z+sq4b.w;
      float mua = sua * (1.0f/LEN), mub = sub * (1.0f/LEN);
      float rsa = rsqrtf(fmaxf(sqa*(1.0f/LEN) - mua*mua, 0.f) + LN_EPS);
      float rsb = rsqrtf(fmaxf(sqb*(1.0f/LEN) - mub*mub, 0.f) + LN_EPS);
      bool mka = mu8 ? (m8[growbase+rg ] != 0) : (m32[growbase+rg ] != 0);
      bool mkb = mu8 ? (m8[growbase+rg8] != 0) : (m32[growbase+rg8] != 0);
      float* orowa = out + (growbase + rg ) * (2*LEN);
      float* orowb = out + (growbase + rg8) * (2*LEN);
      #pragma unroll
      for (int nt = 0; nt < 4; nt++){
        const int c0 = cbase + nt*8 + 2*tig;
        float2 gg = *(const float2*)&sGam[c0];
        float2 be = *(const float2*)&sBet[c0];
        float* a = acc[nt];
        float v0 = (a[0]-mua)*rsa*gg.x + be.x;
        float v1 = (a[1]-mua)*rsa*gg.y + be.y;
        float v2 = (a[2]-mub)*rsb*gg.x + be.x;
        float v3 = (a[3]-mub)*rsb*gg.y + be.y;
        v0 = mka ? fmaxf(v0, 0.f) : NEG_FILL;
        v1 = mka ? fmaxf(v1, 0.f) : NEG_FILL;
        v2 = mkb ? fmaxf(v2, 0.f) : NEG_FILL;
        v3 = mkb ? fmaxf(v3, 0.f) : NEG_FILL;
        __stcs((float2*)(orowa + c0), make_float2(v0, v1));
        __stcs((float2*)(orowb + c0), make_float2(v2, v3));
        pm[2*nt]   = fmaxf(pm[2*nt],   fmaxf(v0, v2));
        pm[2*nt+1] = fmaxf(pm[2*nt+1], fmaxf(v1, v3));
      }
    }

    /* STS held tile t+1 into other buffer; then issue LDG for t+2 (drains under
       the next iteration's MMA+epilogue) */
    if (t + 1 < te){
      sts_held((unsigned*)(smu + (cur ? SM_X0 : SM_X1)), st, srow, scb);
      if (t + 2 < te) ldg_tile(st, X + (size_t)(t+2)*TILE_M*LEN, srow, scb);
    }

    /* batch boundary (32 tiles/batch): flush pool */
    if (t == te-1 || ((t+1) >> 5) != (t >> 5)){
      const int b = t >> 5;
      #pragma unroll
      for (int i = 0; i < 8; i++){
        pm[i] = fmaxf(pm[i], __shfl_xor_sync(0xffffffffu, pm[i], 4));
        pm[i] = fmaxf(pm[i], __shfl_xor_sync(0xffffffffu, pm[i], 8));
        pm[i] = fmaxf(pm[i], __shfl_xor_sync(0xffffffffu, pm[i], 16));
      }
      if (lane < 4){   /* g==0 lanes: tig = lane */
        unsigned* pp = g_pool + b*LEN;
        #pragma unroll
        for (int nt = 0; nt < 4; nt++){
          int c0 = cbase + nt*8 + 2*lane;
          atomicMax(pp + c0,     f2o(pm[2*nt]));
          atomicMax(pp + c0 + 1, f2o(pm[2*nt+1]));
        }
      }
      #pragma unroll
      for (int i = 0; i < 8; i++) pm[i] = NEG_FILL;
    }
    __syncthreads();   /* staged buffer visible before next iter reads it */
  }
}

/* ---- broadcast pooled max into second half of output ---- */
__global__ void __launch_bounds__(256,8)
broadcast_kernel(float* __restrict__ out){
  const int b   = blockIdx.x >> 3;          /* batch */
  const int rch = (blockIdx.x & 7) * 256;   /* row chunk within batch */
  const int c4  = threadIdx.x & 31;
  const int w   = threadIdx.x >> 5;
  uint4 p = *(const uint4*)(g_pool + b*LEN + c4*4);
  float4 v = make_float4(o2f(p.x), o2f(p.y), o2f(p.z), o2f(p.w));
  float* base = out + ((size_t)b*NN + rch) * (2*LEN) + LEN + c4*4;
  #pragma unroll
  for (int it = 0; it < 32; it++)
    __stcs((float4*)(base + (size_t)(w + it*8) * (2*LEN)), v);
}

extern "C" void kernel_launch(void* const* d_in, const int* in_sizes, int n_in,
                              void* d_out, int out_size){
  (void)in_sizes; (void)n_in; (void)out_size;
  const float* X    = (const float*)d_in[0];
  const void*  mask = d_in[1];
  const float* W1   = (const float*)d_in[2];
  const float* b1   = (const float*)d_in[3];
  const float* W2   = (const float*)d_in[4];
  const float* b2   = (const float*)d_in[5];
  const float* gm   = (const float*)d_in[6];
  const float* bt   = (const float*)d_in[7];
  float* out = (float*)d_out;

  cudaFuncSetAttribute(mlp_kernel, cudaFuncAttributeMaxDynamicSharedMemorySize, SMEM_BYTES);

  int dev = 0; cudaGetDevice(&dev);
  int sms = 148;
  cudaDeviceGetAttribute(&sms, cudaDevAttrMultiProcessorCount, dev);
  if (sms <= 0) sms = 148;

  prep_kernel<<<(128*64 + LEN + NB*LEN + 255)/256, 256>>>(W1, b1, W2, b2,
                                                          (const unsigned*)mask);
  mlp_kernel<<<sms*2, NTHREADS, SMEM_BYTES>>>(X, mask, gm, bt, out);
  broadcast_kernel<<<NB*8, 256>>>(out);
}

// round 14
// speedup vs baseline: 1.5553x; 1.0973x over previous
#include <cuda_runtime.h>
#include <cuda_bf16.h>
#include <cstdint>
#include <cstddef>

#define LEN 128
#define HID 64
#define NB 256
#define NN 2048
#define NROWS (NB*NN)          /* 524288 */
#define TILE_M 64
#define NTILES (NROWS/TILE_M)  /* 8192, 32 tiles per batch */
#define NEG_FILL -1.0e9f
#define LN_EPS 1e-3f
#define NTHREADS 512

/* bf16x2 plane-packed layouts over kpair q (=k/2, 0..63): plane p=q%4, j=q/4.
   Strides in 32-bit words. */
#define WCST 20                    /* W col stride */
#define WPST (128*WCST + 8)        /* 2568 W plane stride */
#define WP_WORDS (4*WPST)          /* 10272 */
#define XRST 20                    /* X row stride */
#define XPST (TILE_M*XRST + 8)     /* 1288 X plane stride */
#define XBUF_WORDS (4*XPST)        /* 5152 per buffer */

/* shared memory layout (words) */
#define SM_W    0
#define SM_CG   WP_WORDS
#define SM_CB   (SM_CG + 128)
#define SM_CC   (SM_CB + 128)
#define SM_X0   (SM_CC + 128)
#define SM_X1   (SM_X0 + XBUF_WORDS)
#define SM_ST   (SM_X1 + XBUF_WORDS)
#define SM_WORDS (SM_ST + TILE_M*8)
#define SMEM_BYTES (SM_WORDS*4)    /* ~86 KB -> 2 CTAs/SM */

__device__ __align__(16) unsigned g_Wpu[WP_WORDS]; /* combined W1@W2 bf16x2, plane-packed */
__device__ float    g_bc[LEN];
__device__ unsigned g_pool[NB*LEN];
__device__ int      g_mask_u8;

__device__ __forceinline__ unsigned f2o(float f){
  unsigned u = __float_as_uint(f);
  return (u & 0x80000000u) ? ~u : (u | 0x80000000u);
}
__device__ __forceinline__ float o2f(unsigned o){
  unsigned u = (o & 0x80000000u) ? (o & 0x7fffffffu) : ~o;
  return __uint_as_float(u);
}
__device__ __forceinline__ unsigned packbf(float lo, float hi){
  unsigned r;
  asm("cvt.rn.bf16x2.f32 %0, %1, %2;" : "=r"(r) : "f"(hi), "f"(lo));
  return r;
}
__device__ __forceinline__ void mma16(float* c, unsigned a0, unsigned a1, unsigned a2,
                                      unsigned a3, unsigned b0, unsigned b1){
  asm volatile(
    "mma.sync.aligned.m16n8k16.row.col.f32.bf16.bf16.f32 "
    "{%0,%1,%2,%3}, {%4,%5,%6,%7}, {%8,%9}, {%0,%1,%2,%3};\n"
    : "+f"(c[0]), "+f"(c[1]), "+f"(c[2]), "+f"(c[3])
    : "r"(a0), "r"(a1), "r"(a2), "r"(a3), "r"(b0), "r"(b1));
}

/* ---- prep: combined weight + bias + pool init + mask probe.
   Index transposed so warp lanes share q (W1 broadcast) and stride col (W2 coalesced). ---- */
__global__ void prep_kernel(const float* __restrict__ W1, const float* __restrict__ b1,
                            const float* __restrict__ W2, const float* __restrict__ b2,
                            const unsigned* __restrict__ mw){
  if (blockIdx.x == 0){
    __shared__ int flag;
    if (threadIdx.x == 0) flag = 0;
    __syncthreads();
    int loc = 0;
    #pragma unroll
    for (int k = 0; k < 4; k++)
      if (mw[threadIdx.x*4 + k] > 1u) loc = 1;   /* u8-packed bools -> words >1 */
    if (loc) flag = 1;
    __syncthreads();
    if (threadIdx.x == 0) g_mask_u8 = flag;
  }
  int i = blockIdx.x*blockDim.x + threadIdx.x;
  if (i < 128*64){                      /* kpair-major: lanes share q, stride col */
    int col = i & 127, q = i >> 7;
    int k0 = 2*q, k1 = 2*q + 1;
    float s0 = 0.f, s1 = 0.f;
    #pragma unroll
    for (int h = 0; h < HID; h++){
      float w2 = W2[h*LEN + col];      /* coalesced across lanes */
      s0 += W1[k0*HID + h] * w2;       /* broadcast across lanes */
      s1 += W1[k1*HID + h] * w2;
    }
    g_Wpu[(q&3)*WPST + col*WCST + (q>>2)] = packbf(s0, s1);
  } else if (i < 128*64 + LEN){
    int c = i - 128*64;
    float s = b2[c];
    #pragma unroll
    for (int h = 0; h < HID; h++) s += b1[h] * W2[h*LEN + c];
    g_bc[c] = s;
  } else if (i < 128*64 + LEN + NB*LEN){
    g_pool[i - (128*64 + LEN)] = f2o(NEG_FILL);
  }
}

/* STS one held tile (4 float4/thread) -> bf16x2 plane-packed buffer */
__device__ __forceinline__ void sts_held(unsigned* xb, const float4* st, int row, int cb){
  #pragma unroll
  for (int i = 0; i < 4; i++){
    int c = cb + 8*i;                /* chunk: floats 4c..4c+3, kpairs 2c, 2c+1 */
    float4 v = st[i];
    int q0 = 2*c, q1 = 2*c + 1;
    xb[(q0&3)*XPST + row*XRST + (q0>>2)] = packbf(v.x, v.y);
    xb[(q1&3)*XPST + row*XRST + (q1>>2)] = packbf(v.z, v.w);
  }
}
__device__ __forceinline__ void ldg_tile(float4* st, const float* __restrict__ src,
                                         int row, int cb){
  #pragma unroll
  for (int i = 0; i < 4; i++)
    st[i] = __ldcs((const float4*)(src + row*LEN + (cb + 8*i)*4));
}

/* ---- fused GEMM(bf16) + bias + LN + ReLU + mask + direct store + pooled max ---- */
__global__ void __launch_bounds__(NTHREADS,2)
mlp_kernel(const float* __restrict__ X, const void* __restrict__ maskp,
           const float* __restrict__ gamma, const float* __restrict__ beta,
           float* __restrict__ out)
{
  extern __shared__ unsigned smu[];
  unsigned* Wp   = smu + SM_W;
  float* sGam    = (float*)(smu + SM_CG);
  float* sBet    = (float*)(smu + SM_CB);
  float* sBia    = (float*)(smu + SM_CC);
  float* stats   = (float*)(smu + SM_ST);

  const int tid  = threadIdx.x;
  const int lane = tid & 31;
  const int wid  = tid >> 5;
  const int g    = lane >> 2, tig = lane & 3;
  const int wm   = wid >> 2,  wn  = wid & 3;   /* 4 m-warps x 4 n-warps; 16 rows/m-warp */
  const int cbase = wn*32;
  const int rb   = wm*16;
  const int srow = tid >> 3, scb = tid & 7;    /* staging: 64 rows x 8 base-chunks */

  #pragma unroll
  for (int i = tid; i < WP_WORDS/4; i += NTHREADS)
    ((uint4*)Wp)[i] = ((const uint4*)g_Wpu)[i];
  if (tid < 128){
    sGam[tid] = gamma[tid];
    sBet[tid] = beta[tid];
    sBia[tid] = g_bc[tid];
  }

  const bool mu8 = (g_mask_u8 != 0);
  const unsigned char* m8  = (const unsigned char*)maskp;
  const int*           m32 = (const int*)maskp;

  const int per = (NTILES + gridDim.x - 1) / gridDim.x;
  const int tb  = blockIdx.x * per;
  const int te  = (tb + per < NTILES) ? tb + per : NTILES;
  if (tb >= te) return;

  float pm[8];
  #pragma unroll
  for (int i = 0; i < 8; i++) pm[i] = NEG_FILL;

  float4 st[4];
  /* prologue: stage tile tb into buf0 (transient), then issue LDG for tb+1 */
  ldg_tile(st, X + (size_t)tb*TILE_M*LEN, srow, scb);
  sts_held(smu + SM_X0, st, srow, scb);
  if (tb + 1 < te) ldg_tile(st, X + (size_t)(tb+1)*TILE_M*LEN, srow, scb);
  __syncthreads();

  for (int t = tb; t < te; t++){
    const int cur = (t - tb) & 1;
    const unsigned* Xs = smu + (cur ? SM_X1 : SM_X0);

    float acc[4][4];
    #pragma unroll
    for (int nt = 0; nt < 4; nt++)
      #pragma unroll
      for (int j = 0; j < 4; j++) acc[nt][j] = 0.f;

    #pragma unroll
    for (int c = 0; c < 4; c++){    /* ksteps s = 2c, 2c+1 */
      uint4 a0 = *(const uint4*)(Xs + tig*XPST + (rb + g    )*XRST + c*4);
      uint4 a1 = *(const uint4*)(Xs + tig*XPST + (rb + g + 8)*XRST + c*4);
      uint4 w4[4];
      #pragma unroll
      for (int nt = 0; nt < 4; nt++)
        w4[nt] = *(const uint4*)(Wp + tig*WPST + (cbase + nt*8 + g)*WCST + c*4);
      #pragma unroll
      for (int nt = 0; nt < 4; nt++){
        mma16(acc[nt], a0.x, a1.x, a0.y, a1.y, w4[nt].x, w4[nt].y);
        mma16(acc[nt], a0.z, a1.z, a0.w, a1.w, w4[nt].z, w4[nt].w);
      }
    }

    /* bias + LN partial stats */
    {
      float s0=0.f, q0=0.f, s1=0.f, q1=0.f;
      #pragma unroll
      for (int nt = 0; nt < 4; nt++){
        float2 bb = *(const float2*)&sBia[cbase + nt*8 + 2*tig];
        float* a = acc[nt];
        a[0]+=bb.x; a[1]+=bb.y; a[2]+=bb.x; a[3]+=bb.y;
        s0 += a[0]+a[1]; q0 += a[0]*a[0]+a[1]*a[1];
        s1 += a[2]+a[3]; q1 += a[2]*a[2]+a[3]*a[3];
      }
      #pragma unroll
      for (int off = 1; off < 4; off <<= 1){
        s0 += __shfl_xor_sync(0xffffffffu, s0, off);
        q0 += __shfl_xor_sync(0xffffffffu, q0, off);
        s1 += __shfl_xor_sync(0xffffffffu, s1, off);
        q1 += __shfl_xor_sync(0xffffffffu, q1, off);
      }
      if (tig == 0){
        stats[(rb+g  )*8 + wn]     = s0;
        stats[(rb+g  )*8 + 4 + wn] = q0;
        stats[(rb+g+8)*8 + wn]     = s1;
        stats[(rb+g+8)*8 + 4 + wn] = q1;
      }
    }
    __syncthreads();                                  /* (B) stats ready; Xs reads done */

    const size_t growbase = (size_t)t * TILE_M;
    {
      const int rg = rb + g, rg8 = rb + g + 8;
      float4 su4a = *(const float4*)&stats[rg *8];
      float4 sq4a = *(const float4*)&stats[rg *8 + 4];
      float4 su4b = *(const float4*)&stats[rg8*8];
      float4 sq4b = *(const float4*)&stats[rg8*8 + 4];
      float sua = su4a.x+su4a.y+su4a.z+su4a.w, sqa = sq4a.x+sq4a.y+sq4a.z+sq4a.w;
      float sub = su4b.x+su4b.y+su4b.z+su4b.w, sqb = sq4b.x+sq4b.y+sq4b.z+sq4b.w;
      float mua = sua * (1.0f/LEN), mub = sub * (1.0f/LEN);
      float rsa = rsqrtf(fmaxf(sqa*(1.0f/LEN) - mua*mua, 0.f) + LN_EPS);
      float rsb = rsqrtf(fmaxf(sqb*(1.0f/LEN) - mub*mub, 0.f) + LN_EPS);
      bool mka = mu8 ? (m8[growbase+rg ] != 0) : (m32[growbase+rg ] != 0);
      bool mkb = mu8 ? (m8[growbase+rg8] != 0) : (m32[growbase+rg8] != 0);
      float* orowa = out + (growbase + rg ) * (2*LEN);
      float* orowb = out + (growbase + rg8) * (2*LEN);
      #pragma unroll
      for (int nt = 0; nt < 4; nt++){
        const int c0 = cbase + nt*8 + 2*tig;
        float2 gg = *(const float2*)&sGam[c0];
        float2 be = *(const float2*)&sBet[c0];
        float* a = acc[nt];
        float v0 = (a[0]-mua)*rsa*gg.x + be.x;
        float v1 = (a[1]-mua)*rsa*gg.y + be.y;
        float v2 = (a[2]-mub)*rsb*gg.x + be.x;
        float v3 = (a[3]-mub)*rsb*gg.y + be.y;
        v0 = mka ? fmaxf(v0, 0.f) : NEG_FILL;
        v1 = mka ? fmaxf(v1, 0.f) : NEG_FILL;
        v2 = mkb ? fmaxf(v2, 0.f) : NEG_FILL;
        v3 = mkb ? fmaxf(v3, 0.f) : NEG_FILL;
        __stcs((float2*)(orowa + c0), make_float2(v0, v1));
        __stcs((float2*)(orowb + c0), make_float2(v2, v3));
        pm[2*nt]   = fmaxf(pm[2*nt],   fmaxf(v0, v2));
        pm[2*nt+1] = fmaxf(pm[2*nt+1], fmaxf(v1, v3));
      }
    }

    /* STS held tile t+1 into other buffer; then issue LDG for t+2 (drains under
       the next iteration's MMA+epilogue) */
    if (t + 1 < te){
      sts_held((unsigned*)(smu + (cur ? SM_X0 : SM_X1)), st, srow, scb);
      if (t + 2 < te) ldg_tile(st, X + (size_t)(t+2)*TILE_M*LEN, srow, scb);
    }

    /* batch boundary (32 tiles/batch): flush pool */
    if (t == te-1 || ((t+1) >> 5) != (t >> 5)){
      const int b = t >> 5;
      #pragma unroll
      for (int i = 0; i < 8; i++){
        pm[i] = fmaxf(pm[i], __shfl_xor_sync(0xffffffffu, pm[i], 4));
        pm[i] = fmaxf(pm[i], __shfl_xor_sync(0xffffffffu, pm[i], 8));
        pm[i] = fmaxf(pm[i], __shfl_xor_sync(0xffffffffu, pm[i], 16));
      }
      if (lane < 4){   /* g==0 lanes: tig = lane */
        unsigned* pp = g_pool + b*LEN;
        #pragma unroll
        for (int nt = 0; nt < 4; nt++){
          int c0 = cbase + nt*8 + 2*lane;
          atomicMax(pp + c0,     f2o(pm[2*nt]));
          atomicMax(pp + c0 + 1, f2o(pm[2*nt+1]));
        }
      }
      #pragma unroll
      for (int i = 0; i < 8; i++) pm[i] = NEG_FILL;
    }
    __syncthreads();   /* staged buffer visible before next iter reads it */
  }
}

/* ---- broadcast pooled max into second half of output (finer grid for balance) ---- */
__global__ void __launch_bounds__(256,8)
broadcast_kernel(float* __restrict__ out){
  const int b   = blockIdx.x >> 4;          /* batch */
  const int rch = (blockIdx.x & 15) * 128;  /* row chunk within batch */
  const int c4  = threadIdx.x & 31;
  const int w   = threadIdx.x >> 5;
  uint4 p = *(const uint4*)(g_pool + b*LEN + c4*4);
  float4 v = make_float4(o2f(p.x), o2f(p.y), o2f(p.z), o2f(p.w));
  float* base = out + ((size_t)b*NN + rch) * (2*LEN) + LEN + c4*4;
  #pragma unroll
  for (int it = 0; it < 16; it++)
    __stcs((float4*)(base + (size_t)(w + it*8) * (2*LEN)), v);
}

extern "C" void kernel_launch(void* const* d_in, const int* in_sizes, int n_in,
                              void* d_out, int out_size){
  (void)in_sizes; (void)n_in; (void)out_size;
  const float* X    = (const float*)d_in[0];
  const void*  mask = d_in[1];
  const float* W1   = (const float*)d_in[2];
  const float* b1   = (const float*)d_in[3];
  const float* W2   = (const float*)d_in[4];
  const float* b2   = (const float*)d_in[5];
  const float* gm   = (const float*)d_in[6];
  const float* bt   = (const float*)d_in[7];
  float* out = (float*)d_out;

  cudaFuncSetAttribute(mlp_kernel, cudaFuncAttributeMaxDynamicSharedMemorySize, SMEM_BYTES);

  int dev = 0; cudaGetDevice(&dev);
  int sms = 148;
  cudaDeviceGetAttribute(&sms, cudaDevAttrMultiProcessorCount, dev);
  if (sms <= 0) sms = 148;

  prep_kernel<<<(128*64 + LEN + NB*LEN + 255)/256, 256>>>(W1, b1, W2, b2,
                                                          (const unsigned*)mask);
  mlp_kernel<<<sms*2, NTHREADS, SMEM_BYTES>>>(X, mask, gm, bt, out);
  broadcast_kernel<<<NB*16, 256>>>(out);
}

// round 15
// speedup vs baseline: 1.6349x; 1.0511x over previous
#include <cuda_runtime.h>
#include <cuda_bf16.h>
#include <cstdint>
#include <cstddef>

#define LEN 128
#define HID 64
#define NB 256
#define NN 2048
#define NROWS (NB*NN)          /* 524288 */
#define TILE_M 64
#define NTILES (NROWS/TILE_M)  /* 8192, 32 tiles per batch */
#define NEG_FILL -1.0e9f
#define LN_EPS 1e-3f
#define NTHREADS 512

/* bf16x2 plane-packed layouts over kpair q (=k/2, 0..63): plane p=q%4, j=q/4.
   Strides in 32-bit words. */
#define WCST 20                    /* W col stride */
#define WPST (128*WCST + 8)        /* 2568 W plane stride */
#define WP_WORDS (4*WPST)          /* 10272 */
#define XRST 20                    /* X row stride */
#define XPST (TILE_M*XRST + 8)     /* 1288 X plane stride */
#define XBUF_WORDS (4*XPST)        /* 5152 per buffer */

/* shared memory layout (words) */
#define SM_W    0
#define SM_CG   WP_WORDS
#define SM_CB   (SM_CG + 128)
#define SM_CC   (SM_CB + 128)
#define SM_X0   (SM_CC + 128)
#define SM_X1   (SM_X0 + XBUF_WORDS)
#define SM_ST   (SM_X1 + XBUF_WORDS)
#define SM_WORDS (SM_ST + TILE_M*8)
#define SMEM_BYTES (SM_WORDS*4)    /* ~86 KB -> 2 CTAs/SM */

__device__ __align__(16) unsigned g_Wpu[WP_WORDS]; /* combined W1@W2 bf16x2, plane-packed */
__device__ float    g_bc[LEN];
__device__ unsigned g_pool[NB*LEN];
__device__ int      g_mask_u8;

__device__ __forceinline__ unsigned f2o(float f){
  unsigned u = __float_as_uint(f);
  return (u & 0x80000000u) ? ~u : (u | 0x80000000u);
}
__device__ __forceinline__ float o2f(unsigned o){
  unsigned u = (o & 0x80000000u) ? (o & 0x7fffffffu) : ~o;
  return __uint_as_float(u);
}
__device__ __forceinline__ unsigned packbf(float lo, float hi){
  unsigned r;
  asm("cvt.rn.bf16x2.f32 %0, %1, %2;" : "=r"(r) : "f"(hi), "f"(lo));
  return r;
}
__device__ __forceinline__ void mma16(float* c, unsigned a0, unsigned a1, unsigned a2,
                                      unsigned a3, unsigned b0, unsigned b1){
  asm volatile(
    "mma.sync.aligned.m16n8k16.row.col.f32.bf16.bf16.f32 "
    "{%0,%1,%2,%3}, {%4,%5,%6,%7}, {%8,%9}, {%0,%1,%2,%3};\n"
    : "+f"(c[0]), "+f"(c[1]), "+f"(c[2]), "+f"(c[3])
    : "r"(a0), "r"(a1), "r"(a2), "r"(a3), "r"(b0), "r"(b1));
}
/* group-scope named barrier: 4 warps (128 threads) of m-group wm */
__device__ __forceinline__ void gbar(int wm){
  asm volatile("bar.sync %0, 128;" :: "r"(wm + 1) : "memory");
}

/* ---- prep: combined weight + bias + pool init + mask probe.
   kpair-major indexing: lanes share q (W1 broadcast) and stride col (W2 coalesced). ---- */
__global__ void prep_kernel(const float* __restrict__ W1, const float* __restrict__ b1,
                            const float* __restrict__ W2, const float* __restrict__ b2,
                            const unsigned* __restrict__ mw){
  if (blockIdx.x == 0){
    __shared__ int flag;
    if (threadIdx.x == 0) flag = 0;
    __syncthreads();
    int loc = 0;
    #pragma unroll
    for (int k = 0; k < 4; k++)
      if (mw[threadIdx.x*4 + k] > 1u) loc = 1;   /* u8-packed bools -> words >1 */
    if (loc) flag = 1;
    __syncthreads();
    if (threadIdx.x == 0) g_mask_u8 = flag;
  }
  int i = blockIdx.x*blockDim.x + threadIdx.x;
  if (i < 128*64){
    int col = i & 127, q = i >> 7;
    int k0 = 2*q, k1 = 2*q + 1;
    float s0 = 0.f, s1 = 0.f;
    #pragma unroll
    for (int h = 0; h < HID; h++){
      float w2 = W2[h*LEN + col];      /* coalesced across lanes */
      s0 += W1[k0*HID + h] * w2;       /* broadcast across lanes */
      s1 += W1[k1*HID + h] * w2;
    }
    g_Wpu[(q&3)*WPST + col*WCST + (q>>2)] = packbf(s0, s1);
  } else if (i < 128*64 + LEN){
    int c = i - 128*64;
    float s = b2[c];
    #pragma unroll
    for (int h = 0; h < HID; h++) s += b1[h] * W2[h*LEN + c];
    g_bc[c] = s;
  } else if (i < 128*64 + LEN + NB*LEN){
    g_pool[i - (128*64 + LEN)] = f2o(NEG_FILL);
  }
}

/* STS one held tile chunk (4 float4/thread) -> bf16x2 plane-packed buffer */
__device__ __forceinline__ void sts_held(unsigned* xb, const float4* st, int row, int cb){
  #pragma unroll
  for (int i = 0; i < 4; i++){
    int c = cb + 8*i;                /* chunk: floats 4c..4c+3, kpairs 2c, 2c+1 */
    float4 v = st[i];
    int q0 = 2*c, q1 = 2*c + 1;
    xb[(q0&3)*XPST + row*XRST + (q0>>2)] = packbf(v.x, v.y);
    xb[(q1&3)*XPST + row*XRST + (q1>>2)] = packbf(v.z, v.w);
  }
}
__device__ __forceinline__ void ldg_tile(float4* st, const float* __restrict__ src,
                                         int row, int cb){
  #pragma unroll
  for (int i = 0; i < 4; i++)
    st[i] = __ldcs((const float4*)(src + row*LEN + (cb + 8*i)*4));
}

/* ---- fused GEMM(bf16) + bias + LN + ReLU + mask + direct store + pooled max.
   CTA = 4 independent 128-thread pipelines (m-groups); rows, staging, stats,
   outputs and pool contributions are all group-local. ---- */
__global__ void __launch_bounds__(NTHREADS,2)
mlp_kernel(const float* __restrict__ X, const void* __restrict__ maskp,
           const float* __restrict__ gamma, const float* __restrict__ beta,
           float* __restrict__ out)
{
  extern __shared__ unsigned smu[];
  unsigned* Wp   = smu + SM_W;
  float* sGam    = (float*)(smu + SM_CG);
  float* sBet    = (float*)(smu + SM_CB);
  float* sBia    = (float*)(smu + SM_CC);
  float* stats   = (float*)(smu + SM_ST);

  const int tid  = threadIdx.x;
  const int lane = tid & 31;
  const int wid  = tid >> 5;
  const int g    = lane >> 2, tig = lane & 3;
  const int wm   = wid >> 2,  wn  = wid & 3;   /* 4 m-groups x 4 n-warps */
  const int cbase = wn*32;
  const int rb   = wm*16;
  const int lt   = tid & 127;                  /* thread within m-group */
  const int srow = rb + (lt >> 3);             /* group-local staging rows */
  const int scb  = lt & 7;

  #pragma unroll
  for (int i = tid; i < WP_WORDS/4; i += NTHREADS)
    ((uint4*)Wp)[i] = ((const uint4*)g_Wpu)[i];
  if (tid < 128){
    sGam[tid] = gamma[tid];
    sBet[tid] = beta[tid];
    sBia[tid] = g_bc[tid];
  }

  const bool mu8 = (g_mask_u8 != 0);
  const unsigned char* m8  = (const unsigned char*)maskp;
  const int*           m32 = (const int*)maskp;

  const int per = (NTILES + gridDim.x - 1) / gridDim.x;
  const int tb  = blockIdx.x * per;
  const int te  = (tb + per < NTILES) ? tb + per : NTILES;
  if (tb >= te) return;

  float pm[8];
  #pragma unroll
  for (int i = 0; i < 8; i++) pm[i] = NEG_FILL;

  float4 st[4];
  /* prologue: stage own rows of tile tb into buf0, then issue LDG for tb+1 */
  ldg_tile(st, X + (size_t)tb*TILE_M*LEN, srow, scb);
  sts_held(smu + SM_X0, st, srow, scb);
  if (tb + 1 < te) ldg_tile(st, X + (size_t)(tb+1)*TILE_M*LEN, srow, scb);
  __syncthreads();   /* W + consts visible to all; after this, groups run free */

  for (int t = tb; t < te; t++){
    const int cur = (t - tb) & 1;
    const unsigned* Xs = smu + (cur ? SM_X1 : SM_X0);

    float acc[4][4];
    #pragma unroll
    for (int nt = 0; nt < 4; nt++)
      #pragma unroll
      for (int j = 0; j < 4; j++) acc[nt][j] = 0.f;

    #pragma unroll
    for (int c = 0; c < 4; c++){    /* ksteps s = 2c, 2c+1 */
      uint4 a0 = *(const uint4*)(Xs + tig*XPST + (rb + g    )*XRST + c*4);
      uint4 a1 = *(const uint4*)(Xs + tig*XPST + (rb + g + 8)*XRST + c*4);
      uint4 w4[4];
      #pragma unroll
      for (int nt = 0; nt < 4; nt++)
        w4[nt] = *(const uint4*)(Wp + tig*WPST + (cbase + nt*8 + g)*WCST + c*4);
      #pragma unroll
      for (int nt = 0; nt < 4; nt++){
        mma16(acc[nt], a0.x, a1.x, a0.y, a1.y, w4[nt].x, w4[nt].y);
        mma16(acc[nt], a0.z, a1.z, a0.w, a1.w, w4[nt].z, w4[nt].w);
      }
    }

    /* bias + LN partial stats */
    {
      float s0=0.f, q0=0.f, s1=0.f, q1=0.f;
      #pragma unroll
      for (int nt = 0; nt < 4; nt++){
        float2 bb = *(const float2*)&sBia[cbase + nt*8 + 2*tig];
        float* a = acc[nt];
        a[0]+=bb.x; a[1]+=bb.y; a[2]+=bb.x; a[3]+=bb.y;
        s0 += a[0]+a[1]; q0 += a[0]*a[0]+a[1]*a[1];
        s1 += a[2]+a[3]; q1 += a[2]*a[2]+a[3]*a[3];
      }
      #pragma unroll
      for (int off = 1; off < 4; off <<= 1){
        s0 += __shfl_xor_sync(0xffffffffu, s0, off);
        q0 += __shfl_xor_sync(0xffffffffu, q0, off);
        s1 += __shfl_xor_sync(0xffffffffu, s1, off);
        q1 += __shfl_xor_sync(0xffffffffu, q1, off);
      }
      if (tig == 0){
        stats[(rb+g  )*8 + wn]     = s0;
        stats[(rb+g  )*8 + 4 + wn] = q0;
        stats[(rb+g+8)*8 + wn]     = s1;
        stats[(rb+g+8)*8 + 4 + wn] = q1;
      }
    }
    gbar(wm);                                    /* group stats ready; group Xs reads done */

    const size_t growbase = (size_t)t * TILE_M;
    {
      const int rg = rb + g, rg8 = rb + g + 8;
      float4 su4a = *(const float4*)&stats[rg *8];
      float4 sq4a = *(const float4*)&stats[rg *8 + 4];
      float4 su4b = *(const float4*)&stats[rg8*8];
      float4 sq4b = *(const float4*)&stats[rg8*8 + 4];
      float sua = su4a.x+su4a.y+su4a.z+su4a.w, sqa = sq4a.x+sq4a.y+sq4a.z+sq4a.w;
      float sub = su4b.x+su4b.y+su4b.z+su4b.w, sqb = sq4b.x+sq4b.y+sq4b.z+sq4b.w;
      float mua = sua * (1.0f/LEN), mub = sub * (1.0f/LEN);
      float rsa = rsqrtf(fmaxf(sqa*(1.0f/LEN) - mua*mua, 0.f) + LN_EPS);
      float rsb = rsqrtf(fmaxf(sqb*(1.0f/LEN) - mub*mub, 0.f) + LN_EPS);
      bool mka = mu8 ? (m8[growbase+rg ] != 0) : (m32[growbase+rg ] != 0);
      bool mkb = mu8 ? (m8[growbase+rg8] != 0) : (m32[growbase+rg8] != 0);
      float* orowa = out + (growbase + rg ) * (2*LEN);
      float* orowb = out + (growbase + rg8) * (2*LEN);
      #pragma unroll
      for (int nt = 0; nt < 4; nt++){
        const int c0 = cbase + nt*8 + 2*tig;
        float2 gg = *(const float2*)&sGam[c0];
        float2 be = *(const float2*)&sBet[c0];
        float* a = acc[nt];
        float v0 = (a[0]-mua)*rsa*gg.x + be.x;
        float v1 = (a[1]-mua)*rsa*gg.y + be.y;
        float v2 = (a[2]-mub)*rsb*gg.x + be.x;
        float v3 = (a[3]-mub)*rsb*gg.y + be.y;
        v0 = mka ? fmaxf(v0, 0.f) : NEG_FILL;
        v1 = mka ? fmaxf(v1, 0.f) : NEG_FILL;
        v2 = mkb ? fmaxf(v2, 0.f) : NEG_FILL;
        v3 = mkb ? fmaxf(v3, 0.f) : NEG_FILL;
        __stcs((float2*)(orowa + c0), make_float2(v0, v1));
        __stcs((float2*)(orowb + c0), make_float2(v2, v3));
        pm[2*nt]   = fmaxf(pm[2*nt],   fmaxf(v0, v2));
        pm[2*nt+1] = fmaxf(pm[2*nt+1], fmaxf(v1, v3));
      }
    }

    /* STS held tile t+1 (own rows) into other buffer; then issue LDG for t+2 */
    if (t + 1 < te){
      sts_held((unsigned*)(smu + (cur ? SM_X0 : SM_X1)), st, srow, scb);
      if (t + 2 < te) ldg_tile(st, X + (size_t)(t+2)*TILE_M*LEN, srow, scb);
    }

    /* batch boundary (32 tiles/batch): flush pool (global atomics, no barrier) */
    if (t == te-1 || ((t+1) >> 5) != (t >> 5)){
      const int b = t >> 5;
      #pragma unroll
      for (int i = 0; i < 8; i++){
        pm[i] = fmaxf(pm[i], __shfl_xor_sync(0xffffffffu, pm[i], 4));
        pm[i] = fmaxf(pm[i], __shfl_xor_sync(0xffffffffu, pm[i], 8));
        pm[i] = fmaxf(pm[i], __shfl_xor_sync(0xffffffffu, pm[i], 16));
      }
      if (lane < 4){   /* g==0 lanes: tig = lane */
        unsigned* pp = g_pool + b*LEN;
        #pragma unroll
        for (int nt = 0; nt < 4; nt++){
          int c0 = cbase + nt*8 + 2*lane;
          atomicMax(pp + c0,     f2o(pm[2*nt]));
          atomicMax(pp + c0 + 1, f2o(pm[2*nt+1]));
        }
      }
      #pragma unroll
      for (int i = 0; i < 8; i++) pm[i] = NEG_FILL;
    }
    gbar(wm);          /* group's staged rows visible before group reads them */
  }
}

/* ---- broadcast pooled max into second half of output ---- */
__global__ void __launch_bounds__(256,8)
broadcast_kernel(float* __restrict__ out){
  const int b   = blockIdx.x >> 4;          /* batch */
  const int rch = (blockIdx.x & 15) * 128;  /* row chunk within batch */
  const int c4  = threadIdx.x & 31;
  const int w   = threadIdx.x >> 5;
  uint4 p = *(const uint4*)(g_pool + b*LEN + c4*4);
  float4 v = make_float4(o2f(p.x), o2f(p.y), o2f(p.z), o2f(p.w));
  float* base = out + ((size_t)b*NN + rch) * (2*LEN) + LEN + c4*4;
  #pragma unroll
  for (int it = 0; it < 16; it++)
    __stcs((float4*)(base + (size_t)(w + it*8) * (2*LEN)), v);
}

extern "C" void kernel_launch(void* const* d_in, const int* in_sizes, int n_in,
                              void* d_out, int out_size){
  (void)in_sizes; (void)n_in; (void)out_size;
  const float* X    = (const float*)d_in[0];
  const void*  mask = d_in[1];
  const float* W1   = (const float*)d_in[2];
  const float* b1   = (const float*)d_in[3];
  const float* W2   = (const float*)d_in[4];
  const float* b2   = (const float*)d_in[5];
  const float* gm   = (const float*)d_in[6];
  const float* bt   = (const float*)d_in[7];
  float* out = (float*)d_out;

  cudaFuncSetAttribute(mlp_kernel, cudaFuncAttributeMaxDynamicSharedMemorySize, SMEM_BYTES);

  int dev = 0; cudaGetDevice(&dev);
  int sms = 148;
  cudaDeviceGetAttribute(&sms, cudaDevAttrMultiProcessorCount, dev);
  if (sms <= 0) sms = 148;

  prep_kernel<<<(128*64 + LEN + NB*LEN + 255)/256, 256>>>(W1, b1, W2, b2,
                                                          (const unsigned*)mask);
  mlp_kernel<<<sms*2, NTHREADS, SMEM_BYTES>>>(X, mask, gm, bt, out);
  broadcast_kernel<<<NB*16, 256>>>(out);
}

// round 16
// speedup vs baseline: 1.6506x; 1.0096x over previous
#include <cuda_runtime.h>
#include <cuda_bf16.h>
#include <cstdint>
#include <cstddef>

#define LEN 128
#define HID 64
#define NB 256
#define NN 2048
#define NROWS (NB*NN)          /* 524288 */
#define TILE_M 64
#define NTILES (NROWS/TILE_M)  /* 8192, 32 tiles per batch */
#define NEG_FILL -1.0e9f
#define LN_EPS 1e-3f
#define NTHREADS 512

/* bf16x2 plane-packed layouts over kpair q (=k/2, 0..63): plane p=q%4, j=q/4.
   Strides in 32-bit words. */
#define WCST 20                    /* W col stride */
#define WPST (128*WCST + 8)        /* 2568 W plane stride */
#define WP_WORDS (4*WPST)          /* 10272 */
#define XRST 20                    /* X row stride */
#define XPST (TILE_M*XRST + 8)     /* 1288 X plane stride */
#define XBUF_WORDS (4*XPST)        /* 5152 per buffer */

/* shared memory layout (words) */
#define SM_W    0
#define SM_CG   WP_WORDS
#define SM_CB   (SM_CG + 128)
#define SM_CC   (SM_CB + 128)
#define SM_X0   (SM_CC + 128)
#define SM_X1   (SM_X0 + XBUF_WORDS)
#define SM_ST   (SM_X1 + XBUF_WORDS)
#define SM_WORDS (SM_ST + TILE_M*8)
#define SMEM_BYTES (SM_WORDS*4)    /* ~86 KB -> 2 CTAs/SM */

__device__ __align__(16) unsigned g_Wpu[WP_WORDS]; /* combined W1@W2 bf16x2, plane-packed */
__device__ float    g_bc[LEN];
__device__ unsigned g_pool[NB*LEN];
__device__ int      g_mask_u8;

__device__ __forceinline__ unsigned f2o(float f){
  unsigned u = __float_as_uint(f);
  return (u & 0x80000000u) ? ~u : (u | 0x80000000u);
}
__device__ __forceinline__ float o2f(unsigned o){
  unsigned u = (o & 0x80000000u) ? (o & 0x7fffffffu) : ~o;
  return __uint_as_float(u);
}
__device__ __forceinline__ unsigned packbf(float lo, float hi){
  unsigned r;
  asm("cvt.rn.bf16x2.f32 %0, %1, %2;" : "=r"(r) : "f"(hi), "f"(lo));
  return r;
}
__device__ __forceinline__ void mma16(float* c, unsigned a0, unsigned a1, unsigned a2,
                                      unsigned a3, unsigned b0, unsigned b1){
  asm volatile(
    "mma.sync.aligned.m16n8k16.row.col.f32.bf16.bf16.f32 "
    "{%0,%1,%2,%3}, {%4,%5,%6,%7}, {%8,%9}, {%0,%1,%2,%3};\n"
    : "+f"(c[0]), "+f"(c[1]), "+f"(c[2]), "+f"(c[3])
    : "r"(a0), "r"(a1), "r"(a2), "r"(a3), "r"(b0), "r"(b1));
}
/* group-scope named barrier: 4 warps (128 threads) of m-group wm */
__device__ __forceinline__ void gbar(int wm){
  asm volatile("bar.sync %0, 128;" :: "r"(wm + 1) : "memory");
}

/* ---- prep: combined weight + bias + pool init + mask probe.
   kpair-major indexing: lanes share q (W1 broadcast) and stride col (W2 coalesced). ---- */
__global__ void prep_kernel(const float* __restrict__ W1, const float* __restrict__ b1,
                            const float* __restrict__ W2, const float* __restrict__ b2,
                            const unsigned* __restrict__ mw){
  if (blockIdx.x == 0){
    __shared__ int flag;
    if (threadIdx.x == 0) flag = 0;
    __syncthreads();
    int loc = 0;
    #pragma unroll
    for (int k = 0; k < 4; k++)
      if (mw[threadIdx.x*4 + k] > 1u) loc = 1;   /* u8-packed bools -> words >1 */
    if (loc) flag = 1;
    __syncthreads();
    if (threadIdx.x == 0) g_mask_u8 = flag;
  }
  int i = blockIdx.x*blockDim.x + threadIdx.x;
  if (i < 128*64){
    int col = i & 127, q = i >> 7;
    int k0 = 2*q, k1 = 2*q + 1;
    float s0 = 0.f, s1 = 0.f;
    #pragma unroll
    for (int h = 0; h < HID; h++){
      float w2 = W2[h*LEN + col];      /* coalesced across lanes */
      s0 += W1[k0*HID + h] * w2;       /* broadcast across lanes */
      s1 += W1[k1*HID + h] * w2;
    }
    g_Wpu[(q&3)*WPST + col*WCST + (q>>2)] = packbf(s0, s1);
  } else if (i < 128*64 + LEN){
    int c = i - 128*64;
    float s = b2[c];
    #pragma unroll
    for (int h = 0; h < HID; h++) s += b1[h] * W2[h*LEN + c];
    g_bc[c] = s;
  } else if (i < 128*64 + LEN + NB*LEN){
    g_pool[i - (128*64 + LEN)] = f2o(NEG_FILL);
  }
}

/* STS one held tile chunk (4 float4/thread) -> bf16x2 plane-packed buffer */
__device__ __forceinline__ void sts_held(unsigned* xb, const float4* st, int row, int cb){
  #pragma unroll
  for (int i = 0; i < 4; i++){
    int c = cb + 8*i;                /* chunk: floats 4c..4c+3, kpairs 2c, 2c+1 */
    float4 v = st[i];
    int q0 = 2*c, q1 = 2*c + 1;
    xb[(q0&3)*XPST + row*XRST + (q0>>2)] = packbf(v.x, v.y);
    xb[(q1&3)*XPST + row*XRST + (q1>>2)] = packbf(v.z, v.w);
  }
}
__device__ __forceinline__ void ldg_tile(float4* st, const float* __restrict__ src,
                                         int row, int cb){
  #pragma unroll
  for (int i = 0; i < 4; i++)
    st[i] = __ldcs((const float4*)(src + row*LEN + (cb + 8*i)*4));
}

/* ---- fused GEMM(bf16) + bias + LN + ReLU + mask + direct store + pooled max.
   CTA = 4 independent 128-thread pipelines (m-groups); ONE group barrier per tile. ---- */
__global__ void __launch_bounds__(NTHREADS,2)
mlp_kernel(const float* __restrict__ X, const void* __restrict__ maskp,
           const float* __restrict__ gamma, const float* __restrict__ beta,
           float* __restrict__ out)
{
  extern __shared__ unsigned smu[];
  unsigned* Wp   = smu + SM_W;
  float* sGam    = (float*)(smu + SM_CG);
  float* sBet    = (float*)(smu + SM_CB);
  float* sBia    = (float*)(smu + SM_CC);
  float* stats   = (float*)(smu + SM_ST);

  const int tid  = threadIdx.x;
  const int lane = tid & 31;
  const int wid  = tid >> 5;
  const int g    = lane >> 2, tig = lane & 3;
  const int wm   = wid >> 2,  wn  = wid & 3;   /* 4 m-groups x 4 n-warps */
  const int cbase = wn*32;
  const int rb   = wm*16;
  const int lt   = tid & 127;                  /* thread within m-group */
  const int srow = rb + (lt >> 3);             /* group-local staging rows */
  const int scb  = lt & 7;

  #pragma unroll
  for (int i = tid; i < WP_WORDS/4; i += NTHREADS)
    ((uint4*)Wp)[i] = ((const uint4*)g_Wpu)[i];
  if (tid < 128){
    sGam[tid] = gamma[tid];
    sBet[tid] = beta[tid];
    sBia[tid] = g_bc[tid];
  }

  const bool mu8 = (g_mask_u8 != 0);
  const unsigned char* m8  = (const unsigned char*)maskp;
  const int*           m32 = (const int*)maskp;

  const int per = (NTILES + gridDim.x - 1) / gridDim.x;
  const int tb  = blockIdx.x * per;
  const int te  = (tb + per < NTILES) ? tb + per : NTILES;
  if (tb >= te) return;

  float pm[8];
  #pragma unroll
  for (int i = 0; i < 8; i++) pm[i] = NEG_FILL;

  float4 st[4];
  /* prologue: stage own rows of tile tb into buf0, then issue LDG for tb+1 */
  ldg_tile(st, X + (size_t)tb*TILE_M*LEN, srow, scb);
  sts_held(smu + SM_X0, st, srow, scb);
  if (tb + 1 < te) ldg_tile(st, X + (size_t)(tb+1)*TILE_M*LEN, srow, scb);
  __syncthreads();   /* W + consts visible to all; after this, groups run free */

  for (int t = tb; t < te; t++){
    const int cur = (t - tb) & 1;
    const unsigned* Xs = smu + (cur ? SM_X1 : SM_X0);
    const size_t growbase = (size_t)t * TILE_M;
    const int rg = rb + g, rg8 = rb + g + 8;

    /* prefetch mask bytes early — latency drains under the MMA */
    bool mka = mu8 ? (m8[growbase+rg ] != 0) : (m32[growbase+rg ] != 0);
    bool mkb = mu8 ? (m8[growbase+rg8] != 0) : (m32[growbase+rg8] != 0);

    float acc[4][4];
    #pragma unroll
    for (int nt = 0; nt < 4; nt++)
      #pragma unroll
      for (int j = 0; j < 4; j++) acc[nt][j] = 0.f;

    #pragma unroll
    for (int c = 0; c < 4; c++){    /* ksteps s = 2c, 2c+1 */
      uint4 a0 = *(const uint4*)(Xs + tig*XPST + (rb + g    )*XRST + c*4);
      uint4 a1 = *(const uint4*)(Xs + tig*XPST + (rb + g + 8)*XRST + c*4);
      uint4 w4[4];
      #pragma unroll
      for (int nt = 0; nt < 4; nt++)
        w4[nt] = *(const uint4*)(Wp + tig*WPST + (cbase + nt*8 + g)*WCST + c*4);
      #pragma unroll
      for (int nt = 0; nt < 4; nt++){
        mma16(acc[nt], a0.x, a1.x, a0.y, a1.y, w4[nt].x, w4[nt].y);
        mma16(acc[nt], a0.z, a1.z, a0.w, a1.w, w4[nt].z, w4[nt].w);
      }
    }

    /* bias + LN partial stats */
    {
      float s0=0.f, q0=0.f, s1=0.f, q1=0.f;
      #pragma unroll
      for (int nt = 0; nt < 4; nt++){
        float2 bb = *(const float2*)&sBia[cbase + nt*8 + 2*tig];
        float* a = acc[nt];
        a[0]+=bb.x; a[1]+=bb.y; a[2]+=bb.x; a[3]+=bb.y;
        s0 += a[0]+a[1]; q0 += a[0]*a[0]+a[1]*a[1];
        s1 += a[2]+a[3]; q1 += a[2]*a[2]+a[3]*a[3];
      }
      #pragma unroll
      for (int off = 1; off < 4; off <<= 1){
        s0 += __shfl_xor_sync(0xffffffffu, s0, off);
        q0 += __shfl_xor_sync(0xffffffffu, q0, off);
        s1 += __shfl_xor_sync(0xffffffffu, s1, off);
        q1 += __shfl_xor_sync(0xffffffffu, q1, off);
      }
      if (tig == 0){
        stats[(rb+g  )*8 + wn]     = s0;
        stats[(rb+g  )*8 + 4 + wn] = q0;
        stats[(rb+g+8)*8 + wn]     = s1;
        stats[(rb+g+8)*8 + 4 + wn] = q1;
      }
    }

    /* STS held tile t+1 (own rows) into the OTHER buffer — before the barrier,
       so one bar.sync covers both stats-visibility and staging-visibility. */
    if (t + 1 < te)
      sts_held((unsigned*)(smu + (cur ? SM_X0 : SM_X1)), st, srow, scb);

    gbar(wm);   /* group stats ready; group Xs(cur) reads done; buf(t+1) staged */

    {
      float4 su4a = *(const float4*)&stats[rg *8];
      float4 sq4a = *(const float4*)&stats[rg *8 + 4];
      float4 su4b = *(const float4*)&stats[rg8*8];
      float4 sq4b = *(const float4*)&stats[rg8*8 + 4];
      float sua = su4a.x+su4a.y+su4a.z+su4a.w, sqa = sq4a.x+sq4a.y+sq4a.z+sq4a.w;
      float sub = su4b.x+su4b.y+su4b.z+su4b.w, sqb = sq4b.x+sq4b.y+sq4b.z+sq4b.w;
      float mua = sua * (1.0f/LEN), mub = sub * (1.0f/LEN);
      float rsa = rsqrtf(fmaxf(sqa*(1.0f/LEN) - mua*mua, 0.f) + LN_EPS);
      float rsb = rsqrtf(fmaxf(sqb*(1.0f/LEN) - mub*mub, 0.f) + LN_EPS);
      float* orowa = out + (growbase + rg ) * (2*LEN);
      float* orowb = out + (growbase + rg8) * (2*LEN);
      #pragma unroll
      for (int nt = 0; nt < 4; nt++){
        const int c0 = cbase + nt*8 + 2*tig;
        float2 gg = *(const float2*)&sGam[c0];
        float2 be = *(const float2*)&sBet[c0];
        float* a = acc[nt];
        float v0 = (a[0]-mua)*rsa*gg.x + be.x;
        float v1 = (a[1]-mua)*rsa*gg.y + be.y;
        float v2 = (a[2]-mub)*rsb*gg.x + be.x;
        float v3 = (a[3]-mub)*rsb*gg.y + be.y;
        v0 = mka ? fmaxf(v0, 0.f) : NEG_FILL;
        v1 = mka ? fmaxf(v1, 0.f) : NEG_FILL;
        v2 = mkb ? fmaxf(v2, 0.f) : NEG_FILL;
        v3 = mkb ? fmaxf(v3, 0.f) : NEG_FILL;
        __stcs((float2*)(orowa + c0), make_float2(v0, v1));
        __stcs((float2*)(orowb + c0), make_float2(v2, v3));
        pm[2*nt]   = fmaxf(pm[2*nt],   fmaxf(v0, v2));
        pm[2*nt+1] = fmaxf(pm[2*nt+1], fmaxf(v1, v3));
      }
    }

    /* issue LDG for tile t+2 (held regs free again; drains under next MMA) */
    if (t + 1 < te && t + 2 < te)
      ldg_tile(st, X + (size_t)(t+2)*TILE_M*LEN, srow, scb);

    /* batch boundary (32 tiles/batch): flush pool (global atomics, no barrier) */
    if (t == te-1 || ((t+1) >> 5) != (t >> 5)){
      const int b = t >> 5;
      #pragma unroll
      for (int i = 0; i < 8; i++){
        pm[i] = fmaxf(pm[i], __shfl_xor_sync(0xffffffffu, pm[i], 4));
        pm[i] = fmaxf(pm[i], __shfl_xor_sync(0xffffffffu, pm[i], 8));
        pm[i] = fmaxf(pm[i], __shfl_xor_sync(0xffffffffu, pm[i], 16));
      }
      if (lane < 4){   /* g==0 lanes: tig = lane */
        unsigned* pp = g_pool + b*LEN;
        #pragma unroll
        for (int nt = 0; nt < 4; nt++){
          int c0 = cbase + nt*8 + 2*lane;
          atomicMax(pp + c0,     f2o(pm[2*nt]));
          atomicMax(pp + c0 + 1, f2o(pm[2*nt+1]));
        }
      }
      #pragma unroll
      for (int i = 0; i < 8; i++) pm[i] = NEG_FILL;
    }
  }
}

/* ---- broadcast pooled max into second half of output ---- */
__global__ void __launch_bounds__(256,8)
broadcast_kernel(float* __restrict__ out){
  const int b   = blockIdx.x >> 4;          /* batch */
  const int rch = (blockIdx.x & 15) * 128;  /* row chunk within batch */
  const int c4  = threadIdx.x & 31;
  const int w   = threadIdx.x >> 5;
  uint4 p = *(const uint4*)(g_pool + b*LEN + c4*4);
  float4 v = make_float4(o2f(p.x), o2f(p.y), o2f(p.z), o2f(p.w));
  float* base = out + ((size_t)b*NN + rch) * (2*LEN) + LEN + c4*4;
  #pragma unroll
  for (int it = 0; it < 16; it++)
    __stcs((float4*)(base + (size_t)(w + it*8) * (2*LEN)), v);
}

extern "C" void kernel_launch(void* const* d_in, const int* in_sizes, int n_in,
                              void* d_out, int out_size){
  (void)in_sizes; (void)n_in; (void)out_size;
  const float* X    = (const float*)d_in[0];
  const void*  mask = d_in[1];
  const float* W1   = (const float*)d_in[2];
  const float* b1   = (const float*)d_in[3];
  const float* W2   = (const float*)d_in[4];
  const float* b2   = (const float*)d_in[5];
  const float* gm   = (const float*)d_in[6];
  const float* bt   = (const float*)d_in[7];
  float* out = (float*)d_out;

  cudaFuncSetAttribute(mlp_kernel, cudaFuncAttributeMaxDynamicSharedMemorySize, SMEM_BYTES);

  int dev = 0; cudaGetDevice(&dev);
  int sms = 148;
  cudaDeviceGetAttribute(&sms, cudaDevAttrMultiProcessorCount, dev);
  if (sms <= 0) sms = 148;

  prep_kernel<<<(128*64 + LEN + NB*LEN + 255)/256, 256>>>(W1, b1, W2, b2,
                                                          (const unsigned*)mask);
  mlp_kernel<<<sms*2, NTHREADS, SMEM_BYTES>>>(X, mask, gm, bt, out);
  broadcast_kernel<<<NB*16, 256>>>(out);
}